// round 2
// baseline (speedup 1.0000x reference)
#include <cuda_runtime.h>
#include <math.h>

#define N 3072
#define F_IN 512
#define NHID 64
#define NHEADS 4
#define NGRAPH 3
#define NCLASS 16
#define ALPHA 0.2f
#define CHUNK 128
#define TN 32

// Scratch (static device globals: allowed; no allocation)
__device__ float g_Wh[NGRAPH * NHEADS * N * NHID];          // 9.4 MB
__device__ float g_f1[NGRAPH * NHEADS * N];
__device__ float g_f2[NGRAPH * NHEADS * N];
__device__ float g_hbuf[NGRAPH * N * NHEADS * NHID];        // 9.4 MB, [g][n][h*64+o]

// ---------------------------------------------------------------------------
// Kernel 1: Wh[g,h,n,o] = sum_f x[n,f] * W[g,h,f,o]
// grid (N/32, 12), block 256. Tile: 32 rows x 64 o. Thread: 4 rows x 2 o.
// ---------------------------------------------------------------------------
__global__ void wh_kernel(const float* __restrict__ x, const float* __restrict__ W) {
    __shared__ float xs[32 * 32];
    __shared__ float Ws[32 * 64];
    int t = threadIdx.x;
    int gh = blockIdx.y;
    int n0 = blockIdx.x * 32;
    int oc = t & 31;     // o = 2*oc, 2*oc+1
    int rg = t >> 5;     // rows rg, rg+8, rg+16, rg+24
    float acc[4][2] = {};
    const float* Wgh = W + (size_t)gh * F_IN * NHID;

    for (int f0 = 0; f0 < F_IN; f0 += 32) {
#pragma unroll
        for (int i = 0; i < 4; i++) {
            int idx = t + 256 * i;
            int row = idx >> 5, fc = idx & 31;
            xs[idx] = x[(size_t)(n0 + row) * F_IN + f0 + fc];
        }
#pragma unroll
        for (int i = 0; i < 8; i++) {
            int idx = t + 256 * i;
            int fc = idx >> 6, o = idx & 63;
            Ws[idx] = Wgh[(size_t)(f0 + fc) * NHID + o];
        }
        __syncthreads();
#pragma unroll
        for (int fc = 0; fc < 32; fc++) {
            float2 wv = *(const float2*)&Ws[fc * 64 + 2 * oc];
#pragma unroll
            for (int rr = 0; rr < 4; rr++) {
                float xv = xs[(rg + 8 * rr) * 32 + fc];
                acc[rr][0] = fmaf(xv, wv.x, acc[rr][0]);
                acc[rr][1] = fmaf(xv, wv.y, acc[rr][1]);
            }
        }
        __syncthreads();
    }
#pragma unroll
    for (int rr = 0; rr < 4; rr++) {
        int row = n0 + rg + 8 * rr;
        float2 v = make_float2(acc[rr][0], acc[rr][1]);
        *(float2*)&g_Wh[((size_t)gh * N + row) * NHID + 2 * oc] = v;
    }
}

// ---------------------------------------------------------------------------
// Kernel 2: f1[g,h,n] = Wh[g,h,n,:]·a1,  f2 = Wh·a2.  One warp per (gh, n).
// grid (N/8, 12), block 256.
// ---------------------------------------------------------------------------
__global__ void f_kernel(const float* __restrict__ a) {
    int gh = blockIdx.y;
    int w = threadIdx.x >> 5, lane = threadIdx.x & 31;
    int n = blockIdx.x * 8 + w;
    const float* whr = g_Wh + ((size_t)gh * N + n) * NHID;
    const float* ag = a + gh * 2 * NHID;   // [a1(64) | a2(64)]
    float wh0 = whr[lane], wh1 = whr[lane + 32];
    float s1 = wh0 * ag[lane] + wh1 * ag[lane + 32];
    float s2 = wh0 * ag[64 + lane] + wh1 * ag[96 + lane];
#pragma unroll
    for (int k = 16; k; k >>= 1) {
        s1 += __shfl_xor_sync(0xffffffffu, s1, k);
        s2 += __shfl_xor_sync(0xffffffffu, s2, k);
    }
    if (lane == 0) { g_f1[gh * N + n] = s1; g_f2[gh * N + n] = s2; }
}

// ---------------------------------------------------------------------------
// Kernel 3: flash-style masked attention + aggregation + ELU.
// grid (N/32, NGRAPH), block 256, 86144 B dyn smem.
// Since e = lrelu(f1+f2) is bounded (|e| < ~6), no max subtraction is needed:
// p = adj ? exp(e) : 0, accumulate sum, divide at end (identical softmax).
// ---------------------------------------------------------------------------
extern __shared__ float smem_raw[];
__global__ void attn_kernel(const int* __restrict__ adj) {
    float* ps     = smem_raw;                                  // [128][4][32]
    int*   adjs   = (int*)(ps + CHUNK * NHEADS * TN);          // [32][129]
    float* f2s    = (float*)(adjs + TN * 129);                 // [4][128]
    float* f1s    = f2s + NHEADS * CHUNK;                      // [4][32]
    float* partial= f1s + NHEADS * TN;                         // [256]
    float* lsum   = partial + 256;                             // [128]

    int t = threadIdx.x;
    int g = blockIdx.y;
    int n0 = blockIdx.x * TN;
    // phase A ids: 2 threads per (h,r), each does 64 strided m
    int q = t >> 7, hr = t & 127, ha = hr >> 5, ra = hr & 31;
    // phase B ids: thread = (h, o)
    int hb = t >> 6, o = t & 63;

    if (t < 128) {
        lsum[t] = 0.f;
        f1s[t] = g_f1[(g * NHEADS + (t >> 5)) * N + n0 + (t & 31)];
    }
    float acc[TN];
#pragma unroll
    for (int r = 0; r < TN; r++) acc[r] = 0.f;

    const int* adjg = adj + ((size_t)g * N + n0) * N;
    const float* whg = g_Wh + ((size_t)(g * NHEADS + hb) * N) * NHID + o;
    __syncthreads();

    for (int m0 = 0; m0 < N; m0 += CHUNK) {
        // stage adj chunk (32 rows x 128, pad 129 -> conflict-free column reads)
#pragma unroll
        for (int i = 0; i < 16; i++) {
            int idx = t + 256 * i;
            int r = idx >> 7, j = idx & 127;
            adjs[r * 129 + j] = adjg[(size_t)r * N + m0 + j];
        }
        // f2 chunk for ALL 4 heads: 512 floats, strided over 256 threads
#pragma unroll
        for (int idx = t; idx < NHEADS * CHUNK; idx += 256) {
            int h = idx >> 7, j = idx & 127;
            f2s[h * CHUNK + j] = g_f2[(g * NHEADS + h) * N + m0 + j];
        }
        __syncthreads();

        // Phase A: p = adj ? exp(lrelu(f1+f2)) : 0
        {
            float f1v = f1s[ha * TN + ra];
            float psumv = 0.f;
#pragma unroll 4
            for (int i = 0; i < 64; i++) {
                int m = q + 2 * i;
                float s = f1v + f2s[ha * CHUNK + m];
                s = s > 0.f ? s : ALPHA * s;
                float p = (adjs[ra * 129 + m] > 0) ? __expf(s) : 0.f;
                psumv += p;
                ps[(m * NHEADS + ha) * TN + ra] = p;
            }
            partial[t] = psumv;
        }
        __syncthreads();

        if (t < 128) lsum[t] += partial[t] + partial[t + 128];

        // Phase B: acc[r] += p[r][m][h] * Wh[m][h][o]   (FFMA-bound)
        {
            const float* wp = whg + (size_t)m0 * NHID;
#pragma unroll 2
            for (int m = 0; m < CHUNK; m++) {
                float w = wp[m * NHID];
                const float4* pr = (const float4*)(ps + (m * NHEADS + hb) * TN);
#pragma unroll
                for (int j = 0; j < 8; j++) {
                    float4 pv = pr[j];
                    acc[4 * j + 0] = fmaf(pv.x, w, acc[4 * j + 0]);
                    acc[4 * j + 1] = fmaf(pv.y, w, acc[4 * j + 1]);
                    acc[4 * j + 2] = fmaf(pv.z, w, acc[4 * j + 2]);
                    acc[4 * j + 3] = fmaf(pv.w, w, acc[4 * j + 3]);
                }
            }
        }
        __syncthreads();
    }

    // normalize + ELU + store transposed layout [g][n][h*64+o]
#pragma unroll
    for (int r = 0; r < TN; r++) {
        float l = lsum[hb * TN + r];
        float v = acc[r] / l;
        v = v > 0.f ? v : expm1f(v);
        g_hbuf[((size_t)g * N + n0 + r) * (NHEADS * NHID) + hb * NHID + o] = v;
    }
}

// ---------------------------------------------------------------------------
// Kernel 4: per-node head: xi = elu(h @ W_int^T + b_int); out = xi_flat @ W_fus^T
//           + b_fus; log_softmax. grid N, block 64.
// ---------------------------------------------------------------------------
__global__ void head_kernel(const float* __restrict__ W_int, const float* __restrict__ b_int,
                            const float* __restrict__ W_fus, const float* __restrict__ b_fus,
                            float* __restrict__ out) {
    __shared__ float hs[NGRAPH * 256];
    __shared__ float xi[NGRAPH * NCLASS];
    int n = blockIdx.x;
    int t = threadIdx.x;
#pragma unroll
    for (int i = 0; i < 12; i++) {
        int idx = t + 64 * i;
        int g = idx >> 8, d = idx & 255;
        hs[idx] = g_hbuf[((size_t)g * N + n) * 256 + d];
    }
    __syncthreads();
    if (t < NGRAPH * NCLASS) {
        int g = t >> 4, c = t & 15;
        float accv = b_int[c];
        const float* wr = W_int + c * 256;
        const float* hr = hs + g * 256;
#pragma unroll 4
        for (int d = 0; d < 256; d++) accv = fmaf(hr[d], wr[d], accv);
        xi[t] = accv > 0.f ? accv : expm1f(accv);
    }
    __syncthreads();
    if (t < NCLASS) {
        float accv = b_fus[t];
        const float* wr = W_fus + t * (NGRAPH * NCLASS);
#pragma unroll
        for (int j = 0; j < NGRAPH * NCLASS; j++) accv = fmaf(xi[j], wr[j], accv);
        float mx = accv;
#pragma unroll
        for (int k = 8; k; k >>= 1) mx = fmaxf(mx, __shfl_xor_sync(0xffffu, mx, k, 16));
        float ex = expf(accv - mx);
        float s = ex;
#pragma unroll
        for (int k = 8; k; k >>= 1) s += __shfl_xor_sync(0xffffu, s, k, 16);
        out[(size_t)n * NCLASS + t] = accv - mx - logf(s);
    }
}

// ---------------------------------------------------------------------------
// Kernel 5: l1_loss = mean(|W_fus|)
// ---------------------------------------------------------------------------
__global__ void l1_kernel(const float* __restrict__ W_fus, float* __restrict__ out) {
    __shared__ float red[256];
    int t = threadIdx.x;
    float s = 0.f;
    for (int i = t; i < NCLASS * NGRAPH * NCLASS; i += 256) s += fabsf(W_fus[i]);
    red[t] = s;
    __syncthreads();
    for (int k = 128; k; k >>= 1) {
        if (t < k) red[t] += red[t + k];
        __syncthreads();
    }
    if (t == 0) out[(size_t)N * NCLASS] = red[0] / (float)(NCLASS * NGRAPH * NCLASS);
}

// ---------------------------------------------------------------------------
extern "C" void kernel_launch(void* const* d_in, const int* in_sizes, int n_in,
                              void* d_out, int out_size) {
    const float* x     = (const float*)d_in[0];
    const int*   adj   = (const int*)d_in[1];
    const float* W     = (const float*)d_in[2];
    const float* a     = (const float*)d_in[3];
    const float* W_int = (const float*)d_in[4];
    const float* b_int = (const float*)d_in[5];
    const float* W_fus = (const float*)d_in[6];
    const float* b_fus = (const float*)d_in[7];
    float* out = (float*)d_out;

    const int attn_smem = (CHUNK * NHEADS * TN + TN * 129 + NHEADS * CHUNK +
                           NHEADS * TN + 256 + 128) * 4;  // 86144 B
    cudaFuncSetAttribute(attn_kernel, cudaFuncAttributeMaxDynamicSharedMemorySize, attn_smem);

    wh_kernel<<<dim3(N / 32, NGRAPH * NHEADS), 256>>>(x, W);
    f_kernel<<<dim3(N / 8, NGRAPH * NHEADS), 256>>>(a);
    attn_kernel<<<dim3(N / TN, NGRAPH), 256, attn_smem>>>(adj);
    head_kernel<<<N, 64>>>(W_int, b_int, W_fus, b_fus, out);
    if (out_size > N * NCLASS) l1_kernel<<<1, 256>>>(W_fus, out);
}

// round 4
// speedup vs baseline: 2.3658x; 2.3658x over previous
#include <cuda_runtime.h>
#include <cuda_bf16.h>
#include <math.h>
#include <stdint.h>

#define N 3072
#define F_IN 512
#define NHID 64
#define NHEADS 4
#define NGRAPH 3
#define NCLASS 16
#define ALPHA 0.2f

// ---------------- scratch globals (no allocation) ----------------
__device__ float g_Wh[NGRAPH * NHEADS * N * NHID];            // [gh][n][o] fp32
__device__ float2 g_E1[NGRAPH * NHEADS * N];                  // {exp(f1), exp(a*f1)}
__device__ float2 g_E2[NGRAPH * NHEADS * N];                  // {exp(f2), exp(a*f2)}
__device__ __nv_bfloat16 g_WhTh[NGRAPH * NHEADS * NHID * N];  // [gh][o][m] hi
__device__ __nv_bfloat16 g_WhTl[NGRAPH * NHEADS * NHID * N];  // [gh][o][m] lo
__device__ float g_hbuf[NGRAPH * N * NHEADS * NHID];          // [g][n][h*64+o]

// ---------------- helpers ----------------
__device__ __forceinline__ uint32_t smem_u32(const void* p) {
    uint32_t a;
    asm("{ .reg .u64 t; cvta.to.shared.u64 t, %1; cvt.u32.u64 %0, t; }" : "=r"(a) : "l"(p));
    return a;
}
__device__ __forceinline__ uint32_t bf16pack(float lo, float hi) {
    uint32_t r;
    asm("cvt.rn.satfinite.bf16x2.f32 %0, %1, %2;" : "=r"(r) : "f"(hi), "f"(lo));
    return r;  // lower 16 bits = lo-arg
}
__device__ __forceinline__ void ldsm4(uint32_t* r, uint32_t addr) {
    asm volatile("ldmatrix.sync.aligned.m8n8.x4.shared.b16 {%0,%1,%2,%3}, [%4];"
                 : "=r"(r[0]), "=r"(r[1]), "=r"(r[2]), "=r"(r[3]) : "r"(addr));
}
__device__ __forceinline__ void mma16816(float* c, const uint32_t* a, const uint32_t* b) {
    asm volatile("mma.sync.aligned.m16n8k16.row.col.f32.bf16.bf16.f32 "
                 "{%0,%1,%2,%3}, {%4,%5,%6,%7}, {%8,%9}, {%0,%1,%2,%3};"
                 : "+f"(c[0]), "+f"(c[1]), "+f"(c[2]), "+f"(c[3])
                 : "r"(a[0]), "r"(a[1]), "r"(a[2]), "r"(a[3]), "r"(b[0]), "r"(b[1]));
}
#define SWZ(x) ((x) ^ ((((uint32_t)(x)) >> 3) & 0x70))

// smem layout for attn (single buffered, bytes)
#define SM_PHI 0        // P hi: [2 khalf][128 row][64 cols bf16 = 128 B] = 32768
#define SM_PLO 32768    // P lo: 32768
#define SM_BHI 65536    // B hi: [2 khalf][64 o][64 cols bf16] = 16384
#define SM_BLO 81920    // B lo: 16384
#define SM_PSUM 98304   // 256 floats
#define ATTN_SMEM 99328

// ---------------------------------------------------------------------------
// Kernel 1: Wh = x @ W per (g,h); also emits WhT split to bf16 hi/lo.
// grid (N/32, 12), block 256.
// ---------------------------------------------------------------------------
__global__ void wh_kernel(const float* __restrict__ x, const float* __restrict__ W) {
    __shared__ float sbuf[3072];
    float* xs = sbuf;            // 32x32
    float* Ws = sbuf + 1024;     // 32x64
    int t = threadIdx.x;
    int gh = blockIdx.y;
    int n0 = blockIdx.x * 32;
    int oc = t & 31;
    int rg = t >> 5;
    float acc[4][2] = {};
    const float* Wgh = W + (size_t)gh * F_IN * NHID;

    for (int f0 = 0; f0 < F_IN; f0 += 32) {
#pragma unroll
        for (int i = 0; i < 4; i++) {
            int idx = t + 256 * i;
            int row = idx >> 5, fc = idx & 31;
            xs[idx] = x[(size_t)(n0 + row) * F_IN + f0 + fc];
        }
#pragma unroll
        for (int i = 0; i < 8; i++) {
            int idx = t + 256 * i;
            int fc = idx >> 6, o = idx & 63;
            Ws[idx] = Wgh[(size_t)(f0 + fc) * NHID + o];
        }
        __syncthreads();
#pragma unroll
        for (int fc = 0; fc < 32; fc++) {
            float2 wv = *(const float2*)&Ws[fc * 64 + 2 * oc];
#pragma unroll
            for (int rr = 0; rr < 4; rr++) {
                float xv = xs[(rg + 8 * rr) * 32 + fc];
                acc[rr][0] = fmaf(xv, wv.x, acc[rr][0]);
                acc[rr][1] = fmaf(xv, wv.y, acc[rr][1]);
            }
        }
        __syncthreads();
    }
    // fp32 Wh out
#pragma unroll
    for (int rr = 0; rr < 4; rr++) {
        int row = n0 + rg + 8 * rr;
        *(float2*)&g_Wh[((size_t)gh * N + row) * NHID + 2 * oc] = make_float2(acc[rr][0], acc[rr][1]);
    }
    // transpose via smem -> WhT bf16 hi/lo
    float* tile = sbuf;  // [64 o][33]
#pragma unroll
    for (int rr = 0; rr < 4; rr++) {
        tile[(2 * oc + 0) * 33 + rg + 8 * rr] = acc[rr][0];
        tile[(2 * oc + 1) * 33 + rg + 8 * rr] = acc[rr][1];
    }
    __syncthreads();
    {
        int o = t & 63, ngrp = t >> 6;
        uint32_t hi4[4], lo4[4];
#pragma unroll
        for (int u = 0; u < 4; u++) {
            int nl = ngrp * 8 + 2 * u;
            float w0 = tile[o * 33 + nl], w1 = tile[o * 33 + nl + 1];
            uint32_t hv = bf16pack(w0, w1);
            float l0 = w0 - __uint_as_float(hv << 16);
            float l1 = w1 - __uint_as_float(hv & 0xffff0000u);
            hi4[u] = hv;
            lo4[u] = bf16pack(l0, l1);
        }
        size_t base = ((size_t)gh * 64 + o) * N + n0 + ngrp * 8;
        *(uint4*)&g_WhTh[base] = make_uint4(hi4[0], hi4[1], hi4[2], hi4[3]);
        *(uint4*)&g_WhTl[base] = make_uint4(lo4[0], lo4[1], lo4[2], lo4[3]);
    }
}

// ---------------------------------------------------------------------------
// Kernel 2: f1/f2 -> E1/E2 exp pairs. One warp per (gh, n).
// ---------------------------------------------------------------------------
__global__ void f_kernel(const float* __restrict__ a) {
    int gh = blockIdx.y;
    int w = threadIdx.x >> 5, lane = threadIdx.x & 31;
    int n = blockIdx.x * 8 + w;
    const float* whr = g_Wh + ((size_t)gh * N + n) * NHID;
    const float* ag = a + gh * 2 * NHID;
    float wh0 = whr[lane], wh1 = whr[lane + 32];
    float s1 = wh0 * ag[lane] + wh1 * ag[lane + 32];
    float s2 = wh0 * ag[64 + lane] + wh1 * ag[96 + lane];
#pragma unroll
    for (int k = 16; k; k >>= 1) {
        s1 += __shfl_xor_sync(0xffffffffu, s1, k);
        s2 += __shfl_xor_sync(0xffffffffu, s2, k);
    }
    if (lane == 0) {
        g_E1[gh * N + n] = make_float2(__expf(s1), __expf(ALPHA * s1));
        g_E2[gh * N + n] = make_float2(__expf(s2), __expf(ALPHA * s2));
    }
}

// ---------------------------------------------------------------------------
// Kernel 3: attention. Block = 128 queries x one (g,h). grid (24, 12), 256 thr.
// p = adj ? max(E1*E2, E1a*E2a) : 0  (exp of lrelu, monotonicity)
// C += Phi*Bhi + Phi*Blo + Plo*Bhi  via mma.sync bf16, fp32 accum.
// ---------------------------------------------------------------------------
extern __shared__ char attn_sm[];
__global__ __launch_bounds__(256, 2) void attn_mma_kernel(const int* __restrict__ adj) {
    char* sm = attn_sm;
    uint32_t smem_base = smem_u32(sm);
    int t = threadIdx.x;
    int wid = t >> 5, lane = t & 31;
    int gh = blockIdx.y, g = gh >> 2, h = gh & 3;
    int n0 = blockIdx.x * 128;

    // phase-A ids: thread = (row, half); covers 64 m per chunk
    int row = t >> 1, half = t & 1;
    float2 E1v = g_E1[gh * N + n0 + row];
    float e1 = E1v.x, e1a = E1v.y;
    float psum = 0.f;
    const int* adjrow = adj + ((size_t)g * N + n0 + row) * N + half * 64;
    const float2* e2g = g_E2 + (size_t)gh * N + half * 64;
    uint32_t p_off = (uint32_t)(half * 16384 + row * 128);

    // B-copy ids: thread = (o, mq); copies 32 m (64 B) hi + lo
    int ob = t >> 2, mq = t & 3;
    const __nv_bfloat16* bh_row = g_WhTh + ((size_t)gh * 64 + ob) * N + mq * 32;
    const __nv_bfloat16* bl_row = g_WhTl + ((size_t)gh * 64 + ob) * N + mq * 32;
    uint32_t b_off_base = (uint32_t)((mq >> 1) * 8192 + ob * 128 + (mq & 1) * 64);

    // mma ids
    int lrow = lane & 7, seg = lane >> 3;
    int arow = wid * 16 + lrow + (seg & 1) * 8;
    uint32_t a_sel = (uint32_t)((seg >> 1) * 16);
    int bnb = lrow + (seg >> 1) * 8;
    uint32_t b_sel = (uint32_t)((seg & 1) * 16);

    float acc[32];
#pragma unroll
    for (int i = 0; i < 32; i++) acc[i] = 0.f;

    for (int c = 0; c < 24; c++) {
        // ---- stage P (compute + bf16 split) ----
        {
            const int4* aj4 = (const int4*)(adjrow + c * 128);
            const float4* e4 = (const float4*)(e2g + c * 128);
#pragma unroll 4
            for (int i = 0; i < 16; i++) {
                float4 ea = e4[2 * i];
                float4 eb = e4[2 * i + 1];
                int4 aj = aj4[i];
                float p0 = aj.x ? fmaxf(e1 * ea.x, e1a * ea.y) : 0.f;
                float p1 = aj.y ? fmaxf(e1 * ea.z, e1a * ea.w) : 0.f;
                float p2 = aj.z ? fmaxf(e1 * eb.x, e1a * eb.y) : 0.f;
                float p3 = aj.w ? fmaxf(e1 * eb.z, e1a * eb.w) : 0.f;
                psum += (p0 + p1) + (p2 + p3);
                uint32_t hiA = bf16pack(p0, p1);
                uint32_t hiB = bf16pack(p2, p3);
                float l0 = p0 - __uint_as_float(hiA << 16);
                float l1 = p1 - __uint_as_float(hiA & 0xffff0000u);
                float l2 = p2 - __uint_as_float(hiB << 16);
                float l3 = p3 - __uint_as_float(hiB & 0xffff0000u);
                uint32_t s0 = SWZ(p_off + 8 * i);
                *(uint2*)(sm + SM_PHI + s0) = make_uint2(hiA, hiB);
                *(uint2*)(sm + SM_PLO + s0) = make_uint2(bf16pack(l0, l1), bf16pack(l2, l3));
            }
        }
        // ---- stage B (copy pre-split WhT) ----
        {
            const uint4* hs = (const uint4*)(bh_row + c * 128);
            const uint4* ls = (const uint4*)(bl_row + c * 128);
#pragma unroll
            for (int jj = 0; jj < 4; jj++) {
                uint32_t s = SWZ(b_off_base + jj * 16);
                *(uint4*)(sm + SM_BHI + s) = hs[jj];
                *(uint4*)(sm + SM_BLO + s) = ls[jj];
            }
        }
        __syncthreads();

        // ---- mma: each warp 16 rows x 64 cols ----
        {
            uint32_t ahB = smem_base + SM_PHI, alB = smem_base + SM_PLO;
            uint32_t bhB = smem_base + SM_BHI, blB = smem_base + SM_BLO;
#pragma unroll
            for (int ks = 0; ks < 8; ks++) {
                uint32_t ao = SWZ((uint32_t)((ks >> 2) * 16384 + arow * 128 + (ks & 3) * 32) + a_sel);
                uint32_t ah[4], al[4];
                ldsm4(ah, ahB + ao);
                ldsm4(al, alB + ao);
                uint32_t bk = (uint32_t)((ks >> 2) * 8192 + (ks & 3) * 32) + b_sel;
#pragma unroll
                for (int ng = 0; ng < 4; ng++) {
                    uint32_t bo = SWZ(bk + (uint32_t)((ng * 16 + bnb) * 128));
                    uint32_t bh[4], bl[4];
                    ldsm4(bh, bhB + bo);
                    ldsm4(bl, blB + bo);
                    mma16816(acc + ng * 8, ah, bh);
                    mma16816(acc + ng * 8 + 4, ah, bh + 2);
                    mma16816(acc + ng * 8, ah, bl);
                    mma16816(acc + ng * 8 + 4, ah, bl + 2);
                    mma16816(acc + ng * 8, al, bh);
                    mma16816(acc + ng * 8 + 4, al, bh + 2);
                }
            }
        }
        __syncthreads();
    }

    // ---- epilogue: normalize, ELU, store ----
    float* psums = (float*)(sm + SM_PSUM);
    psums[t] = psum;
    __syncthreads();
    int gID = lane >> 2, tig = lane & 3;
    int rA = wid * 16 + gID, rB = rA + 8;
    float invA = 1.f / (psums[2 * rA] + psums[2 * rA + 1]);
    float invB = 1.f / (psums[2 * rB] + psums[2 * rB + 1]);
    float* outA = &g_hbuf[((size_t)g * N + n0 + rA) * 256 + h * 64];
    float* outB = &g_hbuf[((size_t)g * N + n0 + rB) * 256 + h * 64];
#pragma unroll
    for (int nt = 0; nt < 8; nt++) {
        int col = nt * 8 + 2 * tig;
        float v0 = acc[nt * 4 + 0] * invA;
        float v1 = acc[nt * 4 + 1] * invA;
        float v2 = acc[nt * 4 + 2] * invB;
        float v3 = acc[nt * 4 + 3] * invB;
        v0 = v0 > 0.f ? v0 : expm1f(v0);
        v1 = v1 > 0.f ? v1 : expm1f(v1);
        v2 = v2 > 0.f ? v2 : expm1f(v2);
        v3 = v3 > 0.f ? v3 : expm1f(v3);
        *(float2*)(outA + col) = make_float2(v0, v1);
        *(float2*)(outB + col) = make_float2(v2, v3);
    }
}

// ---------------------------------------------------------------------------
// Kernel 4: head. 8 nodes/block, 128 threads, grid N/8.
// ---------------------------------------------------------------------------
__global__ void head_kernel(const float* __restrict__ W_int, const float* __restrict__ b_int,
                            const float* __restrict__ W_fus, const float* __restrict__ b_fus,
                            float* __restrict__ out) {
    __shared__ float hs[8][776];
    __shared__ float wint_s[16][257];
    __shared__ float wfus_s[16][49];
    __shared__ float xis[8][49];
    int n0 = blockIdx.x * 8;
    int t = threadIdx.x;

    for (int i = t; i < NCLASS * 256; i += 128) wint_s[i >> 8][i & 255] = W_int[i];
    for (int i = t; i < NCLASS * 48; i += 128) wfus_s[i / 48][i % 48] = W_fus[i];
    for (int i = t; i < 8 * 768; i += 128) {
        int nl = i / 768, rem = i - nl * 768;
        int g = rem >> 8, d = rem & 255;
        hs[nl][rem] = g_hbuf[((size_t)g * N + n0 + nl) * 256 + d];
    }
    __syncthreads();

    int nl = t >> 4, c = t & 15;
    {
        float bi = b_int[c];
        const float* wr = wint_s[c];
#pragma unroll
        for (int g = 0; g < NGRAPH; g++) {
            float acc = bi;
            const float* hr = &hs[nl][g * 256];
#pragma unroll 4
            for (int d = 0; d < 256; d++) acc = fmaf(hr[d], wr[d], acc);
            xis[nl][g * 16 + c] = acc > 0.f ? acc : expm1f(acc);
        }
    }
    __syncthreads();
    {
        float acc = b_fus[c];
        const float* wr = wfus_s[c];
        const float* xr = xis[nl];
#pragma unroll
        for (int j = 0; j < 48; j++) acc = fmaf(xr[j], wr[j], acc);
        float mx = acc;
#pragma unroll
        for (int k = 8; k; k >>= 1) mx = fmaxf(mx, __shfl_xor_sync(0xffffffffu, mx, k, 16));
        float s = expf(acc - mx);
#pragma unroll
        for (int k = 8; k; k >>= 1) s += __shfl_xor_sync(0xffffffffu, s, k, 16);
        out[(size_t)(n0 + nl) * NCLASS + c] = acc - mx - logf(s);
    }
}

// ---------------------------------------------------------------------------
// Kernel 5: l1_loss = mean(|W_fus|)
// ---------------------------------------------------------------------------
__global__ void l1_kernel(const float* __restrict__ W_fus, float* __restrict__ out) {
    __shared__ float red[256];
    int t = threadIdx.x;
    float s = 0.f;
    for (int i = t; i < NCLASS * NGRAPH * NCLASS; i += 256) s += fabsf(W_fus[i]);
    red[t] = s;
    __syncthreads();
    for (int k = 128; k; k >>= 1) {
        if (t < k) red[t] += red[t + k];
        __syncthreads();
    }
    if (t == 0) out[(size_t)N * NCLASS] = red[0] / (float)(NCLASS * NGRAPH * NCLASS);
}

// ---------------------------------------------------------------------------
extern "C" void kernel_launch(void* const* d_in, const int* in_sizes, int n_in,
                              void* d_out, int out_size) {
    const float* x     = (const float*)d_in[0];
    const int*   adj   = (const int*)d_in[1];
    const float* W     = (const float*)d_in[2];
    const float* a     = (const float*)d_in[3];
    const float* W_int = (const float*)d_in[4];
    const float* b_int = (const float*)d_in[5];
    const float* W_fus = (const float*)d_in[6];
    const float* b_fus = (const float*)d_in[7];
    float* out = (float*)d_out;

    cudaFuncSetAttribute(attn_mma_kernel, cudaFuncAttributeMaxDynamicSharedMemorySize, ATTN_SMEM);

    wh_kernel<<<dim3(N / 32, NGRAPH * NHEADS), 256>>>(x, W);
    f_kernel<<<dim3(N / 8, NGRAPH * NHEADS), 256>>>(a);
    attn_mma_kernel<<<dim3(N / 128, NGRAPH * NHEADS), 256, ATTN_SMEM>>>(adj);
    head_kernel<<<N / 8, 128>>>(W_int, b_int, W_fus, b_fus, out);
    if (out_size > N * NCLASS) l1_kernel<<<1, 256>>>(W_fus, out);
}

// round 5
// speedup vs baseline: 4.3015x; 1.8182x over previous
#include <cuda_runtime.h>
#include <cuda_bf16.h>
#include <math.h>
#include <stdint.h>

#define N 3072
#define F_IN 512
#define NHID 64
#define NHEADS 4
#define NGRAPH 3
#define NCLASS 16
#define ALPHA 0.2f

// ---------------- scratch globals (no allocation) ----------------
__device__ float g_Wh[NGRAPH * NHEADS * N * NHID];            // [gh][n][o] fp32
__device__ float2 g_E1[NGRAPH * NHEADS * N];                  // {exp(f1), exp(a*f1)}
__device__ float2 g_E2[NGRAPH * NHEADS * N];                  // {exp(f2), exp(a*f2)}
__device__ __nv_bfloat16 g_WhTh[NGRAPH * NHEADS * NHID * N];  // [gh][o][m] hi (attn B)
__device__ __nv_bfloat16 g_xh[N * F_IN];                      // x bf16 hi
__device__ __nv_bfloat16 g_xl[N * F_IN];                      // x bf16 lo
__device__ __nv_bfloat16 g_WTh[NGRAPH * NHEADS * NHID * F_IN];// W^T [gh][o][f] hi
__device__ __nv_bfloat16 g_WTl[NGRAPH * NHEADS * NHID * F_IN];// W^T lo
__device__ uint32_t g_adjbits[NGRAPH * N * (N / 32)];         // adj bitmask
__device__ float g_hbuf[NGRAPH * N * NHEADS * NHID];          // [g][n][h*64+o]

// ---------------- helpers ----------------
__device__ __forceinline__ uint32_t smem_u32(const void* p) {
    uint32_t a;
    asm("{ .reg .u64 t; cvta.to.shared.u64 t, %1; cvt.u32.u64 %0, t; }" : "=r"(a) : "l"(p));
    return a;
}
__device__ __forceinline__ uint32_t bf16pack(float lo, float hi) {
    uint32_t r;
    asm("cvt.rn.satfinite.bf16x2.f32 %0, %1, %2;" : "=r"(r) : "f"(hi), "f"(lo));
    return r;  // low 16 bits = lo-arg
}
__device__ __forceinline__ void ldsm4(uint32_t* r, uint32_t addr) {
    asm volatile("ldmatrix.sync.aligned.m8n8.x4.shared.b16 {%0,%1,%2,%3}, [%4];"
                 : "=r"(r[0]), "=r"(r[1]), "=r"(r[2]), "=r"(r[3]) : "r"(addr));
}
__device__ __forceinline__ void mma16816(float* c, const uint32_t* a, const uint32_t* b) {
    asm volatile("mma.sync.aligned.m16n8k16.row.col.f32.bf16.bf16.f32 "
                 "{%0,%1,%2,%3}, {%4,%5,%6,%7}, {%8,%9}, {%0,%1,%2,%3};"
                 : "+f"(c[0]), "+f"(c[1]), "+f"(c[2]), "+f"(c[3])
                 : "r"(a[0]), "r"(a[1]), "r"(a[2]), "r"(a[3]), "r"(b[0]), "r"(b[1]));
}
#define SWZ(x) ((x) ^ ((((uint32_t)(x)) >> 3) & 0x70))

// ---------------------------------------------------------------------------
// Prep 1: split x to bf16 hi/lo. 4 floats/thread.
// ---------------------------------------------------------------------------
__global__ void xsplit_kernel(const float* __restrict__ x) {
    int idx = blockIdx.x * 256 + threadIdx.x;
    float4 v = ((const float4*)x)[idx];
    uint32_t h0 = bf16pack(v.x, v.y), h1 = bf16pack(v.z, v.w);
    float l0 = v.x - __uint_as_float(h0 << 16);
    float l1 = v.y - __uint_as_float(h0 & 0xffff0000u);
    float l2 = v.z - __uint_as_float(h1 << 16);
    float l3 = v.w - __uint_as_float(h1 & 0xffff0000u);
    *(uint2*)&g_xh[(size_t)idx * 4] = make_uint2(h0, h1);
    *(uint2*)&g_xl[(size_t)idx * 4] = make_uint2(bf16pack(l0, l1), bf16pack(l2, l3));
}

// ---------------------------------------------------------------------------
// Prep 2: W [gh][512][64] -> W^T [gh][64][512] bf16 hi/lo. grid (8, 12).
// ---------------------------------------------------------------------------
__global__ void wsplit_kernel(const float* __restrict__ W) {
    __shared__ float tile[64][65];
    int t = threadIdx.x;
    int gh = blockIdx.y, f0 = blockIdx.x * 64;
    const float* Wgh = W + (size_t)gh * F_IN * NHID + (size_t)f0 * NHID;
#pragma unroll
    for (int i = 0; i < 16; i++) {
        int idx = t + 256 * i;
        tile[idx >> 6][idx & 63] = Wgh[idx];
    }
    __syncthreads();
    int o = t >> 2, fq = t & 3;
    size_t base = ((size_t)gh * 64 + o) * F_IN + f0 + fq * 16;
#pragma unroll
    for (int j = 0; j < 8; j++) {
        int f = fq * 16 + 2 * j;
        float w0 = tile[f][o], w1 = tile[f + 1][o];
        uint32_t hv = bf16pack(w0, w1);
        float l0 = w0 - __uint_as_float(hv << 16);
        float l1 = w1 - __uint_as_float(hv & 0xffff0000u);
        *(uint32_t*)&g_WTh[base + 2 * j] = hv;
        *(uint32_t*)&g_WTl[base + 2 * j] = bf16pack(l0, l1);
    }
}

// ---------------------------------------------------------------------------
// Prep 3: adj -> bitmask via ballot. 1024 ints per warp.
// ---------------------------------------------------------------------------
__global__ void adjpack_kernel(const int* __restrict__ adj) {
    int lane = threadIdx.x & 31;
    size_t wid = ((size_t)blockIdx.x * 256 + threadIdx.x) >> 5;
    size_t base = wid * 1024;
    uint32_t myw = 0;
#pragma unroll
    for (int i = 0; i < 32; i++) {
        int v = adj[base + i * 32 + lane];
        uint32_t b = __ballot_sync(0xffffffffu, v > 0);
        if (lane == i) myw = b;
    }
    g_adjbits[base / 32 + lane] = myw;
}

// ---------------------------------------------------------------------------
// Kernel 1: Wh = x @ W via mma.sync, 3-term bf16 split (fp32-accurate).
// grid (24, 12), 256 thr. Outputs g_Wh fp32 + g_WhTh bf16 transposed.
// smem: AH 16K | AL 16K | BH 8K | BL 8K  (49152; epilogue reuses as fp32 tile)
// ---------------------------------------------------------------------------
extern __shared__ char whsm[];
__global__ __launch_bounds__(256, 2) void wh_mma_kernel() {
    char* sm = whsm;
    uint32_t smb = smem_u32(sm);
    int t = threadIdx.x;
    int wid = t >> 5, lane = t & 31;
    int gh = blockIdx.y;
    int n0 = blockIdx.x * 128;

    int lrow = lane & 7, seg = lane >> 3;
    int arow = wid * 16 + lrow + (seg & 1) * 8;
    uint32_t a_sel = (uint32_t)((seg >> 1) * 16);
    int bnb = lrow + (seg >> 1) * 8;
    uint32_t b_sel = (uint32_t)((seg & 1) * 16);

    // staging ids
    int rowA = t >> 1, halfA = t & 1;                  // A: 32 k each
    int ob = t >> 2, qb = t & 3;                       // B: 16 f each

    float acc[32];
#pragma unroll
    for (int i = 0; i < 32; i++) acc[i] = 0.f;

    for (int f0 = 0; f0 < F_IN; f0 += 64) {
        // stage A (x) hi/lo
        {
            const uint4* sh = (const uint4*)&g_xh[(size_t)(n0 + rowA) * F_IN + f0 + halfA * 32];
            const uint4* sl = (const uint4*)&g_xl[(size_t)(n0 + rowA) * F_IN + f0 + halfA * 32];
#pragma unroll
            for (int j = 0; j < 4; j++) {
                uint32_t s = SWZ((uint32_t)(rowA * 128 + halfA * 64 + j * 16));
                *(uint4*)(sm + s) = sh[j];
                *(uint4*)(sm + 16384 + s) = sl[j];
            }
        }
        // stage B (W^T) hi/lo
        {
            const uint4* sh = (const uint4*)&g_WTh[((size_t)gh * 64 + ob) * F_IN + f0 + qb * 16];
            const uint4* sl = (const uint4*)&g_WTl[((size_t)gh * 64 + ob) * F_IN + f0 + qb * 16];
#pragma unroll
            for (int j = 0; j < 2; j++) {
                uint32_t s = SWZ((uint32_t)(ob * 128 + qb * 32 + j * 16));
                *(uint4*)(sm + 32768 + s) = sh[j];
                *(uint4*)(sm + 40960 + s) = sl[j];
            }
        }
        __syncthreads();
#pragma unroll
        for (int ks = 0; ks < 4; ks++) {
            uint32_t ao = SWZ((uint32_t)(arow * 128 + ks * 32) + a_sel);
            uint32_t ah[4], al[4];
            ldsm4(ah, smb + ao);
            ldsm4(al, smb + 16384 + ao);
#pragma unroll
            for (int ng = 0; ng < 4; ng++) {
                uint32_t bo = SWZ((uint32_t)((ng * 16 + bnb) * 128 + ks * 32) + b_sel);
                uint32_t bh[4], bl[4];
                ldsm4(bh, smb + 32768 + bo);
                ldsm4(bl, smb + 40960 + bo);
                mma16816(acc + ng * 8, ah, bh);
                mma16816(acc + ng * 8 + 4, ah, bh + 2);
                mma16816(acc + ng * 8, ah, bl);
                mma16816(acc + ng * 8 + 4, ah, bl + 2);
                mma16816(acc + ng * 8, al, bh);
                mma16816(acc + ng * 8 + 4, al, bh + 2);
            }
        }
        __syncthreads();
    }

    // epilogue: fp32 Wh + staged transpose -> bf16 WhT(hi)
    int gID = lane >> 2, tig = lane & 3;
    int rA = wid * 16 + gID, rB = rA + 8;
    float* ftile = (float*)sm;  // [128][66]
#pragma unroll
    for (int nt = 0; nt < 4; nt++) {
        int col = nt * 16 + 2 * tig;  // acc layout: ng-major (ng=nt? acc[ng*8+...])
        (void)col;
    }
#pragma unroll
    for (int ng = 0; ng < 4; ng++) {
        int col = ng * 16 + 2 * tig;
        // n8 tile 0: cols col, col+1 ; tile 1: cols col+8
        *(float2*)&g_Wh[((size_t)gh * N + n0 + rA) * NHID + col] = make_float2(acc[ng * 8 + 0], acc[ng * 8 + 1]);
        *(float2*)&g_Wh[((size_t)gh * N + n0 + rB) * NHID + col] = make_float2(acc[ng * 8 + 2], acc[ng * 8 + 3]);
        *(float2*)&g_Wh[((size_t)gh * N + n0 + rA) * NHID + col + 8] = make_float2(acc[ng * 8 + 4], acc[ng * 8 + 5]);
        *(float2*)&g_Wh[((size_t)gh * N + n0 + rB) * NHID + col + 8] = make_float2(acc[ng * 8 + 6], acc[ng * 8 + 7]);
        ftile[rA * 66 + col] = acc[ng * 8 + 0];
        ftile[rA * 66 + col + 1] = acc[ng * 8 + 1];
        ftile[rB * 66 + col] = acc[ng * 8 + 2];
        ftile[rB * 66 + col + 1] = acc[ng * 8 + 3];
        ftile[rA * 66 + col + 8] = acc[ng * 8 + 4];
        ftile[rA * 66 + col + 9] = acc[ng * 8 + 5];
        ftile[rB * 66 + col + 8] = acc[ng * 8 + 6];
        ftile[rB * 66 + col + 9] = acc[ng * 8 + 7];
    }
    __syncthreads();
    {
        int o = t >> 2, rq = t & 3;
        size_t base = ((size_t)gh * 64 + o) * N + n0 + rq * 32;
#pragma unroll
        for (int j = 0; j < 16; j++) {
            int r = rq * 32 + 2 * j;
            *(uint32_t*)&g_WhTh[base + 2 * j] = bf16pack(ftile[r * 66 + o], ftile[(r + 1) * 66 + o]);
        }
    }
}

// ---------------------------------------------------------------------------
// Kernel 2: f1/f2 -> E pairs. One warp per (gh, n).
// ---------------------------------------------------------------------------
__global__ void f_kernel(const float* __restrict__ a) {
    int gh = blockIdx.y;
    int w = threadIdx.x >> 5, lane = threadIdx.x & 31;
    int n = blockIdx.x * 8 + w;
    const float* whr = g_Wh + ((size_t)gh * N + n) * NHID;
    const float* ag = a + gh * 2 * NHID;
    float wh0 = whr[lane], wh1 = whr[lane + 32];
    float s1 = wh0 * ag[lane] + wh1 * ag[lane + 32];
    float s2 = wh0 * ag[64 + lane] + wh1 * ag[96 + lane];
#pragma unroll
    for (int k = 16; k; k >>= 1) {
        s1 += __shfl_xor_sync(0xffffffffu, s1, k);
        s2 += __shfl_xor_sync(0xffffffffu, s2, k);
    }
    if (lane == 0) {
        g_E1[gh * N + n] = make_float2(__expf(s1), __expf(ALPHA * s1));
        g_E2[gh * N + n] = make_float2(__expf(s2), __expf(ALPHA * s2));
    }
}

// ---------------------------------------------------------------------------
// Kernel 3: attention, single-bf16-term mma. grid (24, 12), 256 thr.
// smem: PHI [2][128][128B]=32K | BHI [2][64][128B]=16K | psum 1K
// ---------------------------------------------------------------------------
#define SM_PHI 0
#define SM_BHI 32768
#define SM_PSUM 49152
#define ATTN_SMEM 50176
extern __shared__ char attn_sm[];
__global__ __launch_bounds__(256, 2) void attn_mma_kernel() {
    char* sm = attn_sm;
    uint32_t smb = smem_u32(sm);
    int t = threadIdx.x;
    int wid = t >> 5, lane = t & 31;
    int gh = blockIdx.y, g = gh >> 2, h = gh & 3;
    int n0 = blockIdx.x * 128;

    int row = t >> 1, half = t & 1;
    float2 E1v = g_E1[gh * N + n0 + row];
    float e1 = E1v.x, e1a = E1v.y;
    float psum = 0.f;
    const uint32_t* bits = g_adjbits + ((size_t)g * N + n0 + row) * 96 + half * 2;
    const float2* e2g = g_E2 + (size_t)gh * N + half * 64;
    uint32_t p_off = (uint32_t)(half * 16384 + row * 128);

    int ob = t >> 2, mq = t & 3;
    const __nv_bfloat16* bh_row = g_WhTh + ((size_t)gh * 64 + ob) * N + mq * 32;
    uint32_t b_off_base = (uint32_t)((mq >> 1) * 8192 + ob * 128 + (mq & 1) * 64);

    int lrow = lane & 7, seg = lane >> 3;
    int arow = wid * 16 + lrow + (seg & 1) * 8;
    uint32_t a_sel = (uint32_t)((seg >> 1) * 16);
    int bnb = lrow + (seg >> 1) * 8;
    uint32_t b_sel = (uint32_t)((seg & 1) * 16);

    float acc[32];
#pragma unroll
    for (int i = 0; i < 32; i++) acc[i] = 0.f;

    for (int c = 0; c < 24; c++) {
        // ---- P stage: p = adj ? max(e1*e2, e1a*e2a) : 0, bf16 hi only ----
        {
            uint2 bw = *(const uint2*)(bits + c * 4);
            const float4* e4 = (const float4*)(e2g + c * 128);
#pragma unroll 4
            for (int i = 0; i < 16; i++) {
                uint32_t w = (i < 8) ? bw.x : bw.y;
                uint32_t nib = w >> ((i & 7) * 4);
                float4 ea = e4[2 * i];
                float4 eb = e4[2 * i + 1];
                float p0 = (nib & 1u) ? fmaxf(e1 * ea.x, e1a * ea.y) : 0.f;
                float p1 = (nib & 2u) ? fmaxf(e1 * ea.z, e1a * ea.w) : 0.f;
                float p2 = (nib & 4u) ? fmaxf(e1 * eb.x, e1a * eb.y) : 0.f;
                float p3 = (nib & 8u) ? fmaxf(e1 * eb.z, e1a * eb.w) : 0.f;
                psum += (p0 + p1) + (p2 + p3);
                uint32_t s0 = SWZ(p_off + 8 * i);
                *(uint2*)(sm + SM_PHI + s0) = make_uint2(bf16pack(p0, p1), bf16pack(p2, p3));
            }
        }
        // ---- B stage: copy pre-split WhT hi ----
        {
            const uint4* hs = (const uint4*)(bh_row + c * 128);
#pragma unroll
            for (int jj = 0; jj < 4; jj++) {
                *(uint4*)(sm + SM_BHI + SWZ(b_off_base + jj * 16)) = hs[jj];
            }
        }
        __syncthreads();
        // ---- mma ----
#pragma unroll
        for (int ks = 0; ks < 8; ks++) {
            uint32_t ao = SWZ((uint32_t)((ks >> 2) * 16384 + arow * 128 + (ks & 3) * 32) + a_sel);
            uint32_t ah[4];
            ldsm4(ah, smb + SM_PHI + ao);
            uint32_t bk = (uint32_t)((ks >> 2) * 8192 + (ks & 3) * 32) + b_sel;
#pragma unroll
            for (int ng = 0; ng < 4; ng++) {
                uint32_t bo = SWZ(bk + (uint32_t)((ng * 16 + bnb) * 128));
                uint32_t bh[4];
                ldsm4(bh, smb + SM_BHI + bo);
                mma16816(acc + ng * 8, ah, bh);
                mma16816(acc + ng * 8 + 4, ah, bh + 2);
            }
        }
        __syncthreads();
    }

    // ---- epilogue ----
    float* psums = (float*)(sm + SM_PSUM);
    psums[t] = psum;
    __syncthreads();
    int gID = lane >> 2, tig = lane & 3;
    int rA = wid * 16 + gID, rB = rA + 8;
    float invA = 1.f / (psums[2 * rA] + psums[2 * rA + 1]);
    float invB = 1.f / (psums[2 * rB] + psums[2 * rB + 1]);
    float* outA = &g_hbuf[((size_t)g * N + n0 + rA) * 256 + h * 64];
    float* outB = &g_hbuf[((size_t)g * N + n0 + rB) * 256 + h * 64];
#pragma unroll
    for (int nt = 0; nt < 8; nt++) {
        int col = nt * 8 + 2 * tig;
        float v0 = acc[nt * 4 + 0] * invA;
        float v1 = acc[nt * 4 + 1] * invA;
        float v2 = acc[nt * 4 + 2] * invB;
        float v3 = acc[nt * 4 + 3] * invB;
        v0 = v0 > 0.f ? v0 : expm1f(v0);
        v1 = v1 > 0.f ? v1 : expm1f(v1);
        v2 = v2 > 0.f ? v2 : expm1f(v2);
        v3 = v3 > 0.f ? v3 : expm1f(v3);
        *(float2*)(outA + col) = make_float2(v0, v1);
        *(float2*)(outB + col) = make_float2(v2, v3);
    }
}

// ---------------------------------------------------------------------------
// Kernel 4: head. 8 nodes/block, 128 threads, float4 inner loops.
// ---------------------------------------------------------------------------
__global__ void head_kernel(const float* __restrict__ W_int, const float* __restrict__ b_int,
                            const float* __restrict__ W_fus, const float* __restrict__ b_fus,
                            float* __restrict__ out) {
    __shared__ float hs[8][776];
    __shared__ float wint_s[16][260];
    __shared__ float wfus_s[16][49];
    __shared__ float xis[8][49];
    int n0 = blockIdx.x * 8;
    int t = threadIdx.x;

    for (int i = t; i < NCLASS * 256; i += 128) wint_s[i >> 8][i & 255] = W_int[i];
    for (int i = t; i < NCLASS * 48; i += 128) wfus_s[i / 48][i % 48] = W_fus[i];
    for (int i = t; i < 8 * 768; i += 128) {
        int nl = i / 768, rem = i - nl * 768;
        int g = rem >> 8, d = rem & 255;
        hs[nl][rem] = g_hbuf[((size_t)g * N + n0 + nl) * 256 + d];
    }
    __syncthreads();

    int nl = t >> 4, c = t & 15;
    {
        float bi = b_int[c];
        const float4* wr = (const float4*)&wint_s[c][0];
#pragma unroll
        for (int g = 0; g < NGRAPH; g++) {
            float a0 = 0.f, a1 = 0.f, a2 = 0.f, a3 = 0.f;
            const float4* hr = (const float4*)&hs[nl][g * 256];
#pragma unroll 8
            for (int d = 0; d < 64; d++) {
                float4 hv = hr[d], wv = wr[d];
                a0 = fmaf(hv.x, wv.x, a0);
                a1 = fmaf(hv.y, wv.y, a1);
                a2 = fmaf(hv.z, wv.z, a2);
                a3 = fmaf(hv.w, wv.w, a3);
            }
            float acc = bi + (a0 + a1) + (a2 + a3);
            xis[nl][g * 16 + c] = acc > 0.f ? acc : expm1f(acc);
        }
    }
    __syncthreads();
    {
        float acc = b_fus[c];
        const float* wr = wfus_s[c];
        const float* xr = xis[nl];
#pragma unroll
        for (int j = 0; j < 48; j++) acc = fmaf(xr[j], wr[j], acc);
        float mx = acc;
#pragma unroll
        for (int k = 8; k; k >>= 1) mx = fmaxf(mx, __shfl_xor_sync(0xffffffffu, mx, k, 16));
        float s = expf(acc - mx);
#pragma unroll
        for (int k = 8; k; k >>= 1) s += __shfl_xor_sync(0xffffffffu, s, k, 16);
        out[(size_t)(n0 + nl) * NCLASS + c] = acc - mx - logf(s);
    }
}

// ---------------------------------------------------------------------------
// Kernel 5: l1_loss = mean(|W_fus|)
// ---------------------------------------------------------------------------
__global__ void l1_kernel(const float* __restrict__ W_fus, float* __restrict__ out) {
    __shared__ float red[256];
    int t = threadIdx.x;
    float s = 0.f;
    for (int i = t; i < NCLASS * NGRAPH * NCLASS; i += 256) s += fabsf(W_fus[i]);
    red[t] = s;
    __syncthreads();
    for (int k = 128; k; k >>= 1) {
        if (t < k) red[t] += red[t + k];
        __syncthreads();
    }
    if (t == 0) out[(size_t)N * NCLASS] = red[0] / (float)(NCLASS * NGRAPH * NCLASS);
}

// ---------------------------------------------------------------------------
extern "C" void kernel_launch(void* const* d_in, const int* in_sizes, int n_in,
                              void* d_out, int out_size) {
    const float* x     = (const float*)d_in[0];
    const int*   adj   = (const int*)d_in[1];
    const float* W     = (const float*)d_in[2];
    const float* a     = (const float*)d_in[3];
    const float* W_int = (const float*)d_in[4];
    const float* b_int = (const float*)d_in[5];
    const float* W_fus = (const float*)d_in[6];
    const float* b_fus = (const float*)d_in[7];
    float* out = (float*)d_out;

    cudaFuncSetAttribute(wh_mma_kernel, cudaFuncAttributeMaxDynamicSharedMemorySize, 49152);
    cudaFuncSetAttribute(attn_mma_kernel, cudaFuncAttributeMaxDynamicSharedMemorySize, ATTN_SMEM);

    xsplit_kernel<<<N * F_IN / 1024, 256>>>(x);
    wsplit_kernel<<<dim3(F_IN / 64, NGRAPH * NHEADS), 256>>>(W);
    adjpack_kernel<<<(NGRAPH * N * N) / (8 * 1024), 256>>>(adj);
    wh_mma_kernel<<<dim3(N / 128, NGRAPH * NHEADS), 256, 49152>>>();
    f_kernel<<<dim3(N / 8, NGRAPH * NHEADS), 256>>>(a);
    attn_mma_kernel<<<dim3(N / 128, NGRAPH * NHEADS), 256, ATTN_SMEM>>>();
    head_kernel<<<N / 8, 128>>>(W_int, b_int, W_fus, b_fus, out);
    if (out_size > N * NCLASS) l1_kernel<<<1, 256>>>(W_fus, out);
}

// round 6
// speedup vs baseline: 5.1902x; 1.2066x over previous
#include <cuda_runtime.h>
#include <cuda_bf16.h>
#include <math.h>
#include <stdint.h>

#define N 3072
#define F_IN 512
#define NHID 64
#define NHEADS 4
#define NGRAPH 3
#define NCLASS 16
#define ALPHA 0.2f

// ---------------- scratch globals (no allocation) ----------------
__device__ float g_Wh[NGRAPH * NHEADS * N * NHID];            // [gh][n][o] fp32
__device__ float2 g_E1[NGRAPH * NHEADS * N];                  // {exp(f1), exp(a*f1)}
__device__ __nv_bfloat16 g_E2b[NGRAPH * NHEADS * N];          // bf16(exp(f2))
__device__ __nv_bfloat16 g_E2ab[NGRAPH * NHEADS * N];         // bf16(exp(a*f2))
__device__ __nv_bfloat16 g_WhTh[NGRAPH * NHEADS * NHID * N];  // [gh][o][m] hi (attn B)
__device__ __nv_bfloat16 g_xh[N * F_IN];                      // x bf16 hi
__device__ __nv_bfloat16 g_xl[N * F_IN];                      // x bf16 lo
__device__ __nv_bfloat16 g_WTh[NGRAPH * NHEADS * NHID * F_IN];// W^T [gh][o][f] hi
__device__ __nv_bfloat16 g_WTl[NGRAPH * NHEADS * NHID * F_IN];// W^T lo
__device__ uint32_t g_adjbits[NGRAPH * N * (N / 32)];         // adj bitmask
__device__ float g_hbuf[NGRAPH * N * NHEADS * NHID];          // [g][n][h*64+o]

// ---------------- helpers ----------------
__device__ __forceinline__ uint32_t smem_u32(const void* p) {
    uint32_t a;
    asm("{ .reg .u64 t; cvta.to.shared.u64 t, %1; cvt.u32.u64 %0, t; }" : "=r"(a) : "l"(p));
    return a;
}
__device__ __forceinline__ uint32_t bf16pack(float lo, float hi) {
    uint32_t r;
    asm("cvt.rn.satfinite.bf16x2.f32 %0, %1, %2;" : "=r"(r) : "f"(hi), "f"(lo));
    return r;  // low 16 bits = lo-arg
}
__device__ __forceinline__ void ldsm4(uint32_t* r, uint32_t addr) {
    asm volatile("ldmatrix.sync.aligned.m8n8.x4.shared.b16 {%0,%1,%2,%3}, [%4];"
                 : "=r"(r[0]), "=r"(r[1]), "=r"(r[2]), "=r"(r[3]) : "r"(addr));
}
__device__ __forceinline__ void mma16816(float* c, const uint32_t* a, const uint32_t* b) {
    asm volatile("mma.sync.aligned.m16n8k16.row.col.f32.bf16.bf16.f32 "
                 "{%0,%1,%2,%3}, {%4,%5,%6,%7}, {%8,%9}, {%0,%1,%2,%3};"
                 : "+f"(c[0]), "+f"(c[1]), "+f"(c[2]), "+f"(c[3])
                 : "r"(a[0]), "r"(a[1]), "r"(a[2]), "r"(a[3]), "r"(b[0]), "r"(b[1]));
}
// p_pair = max(e1p*u, e1ap*v)  (bf16x2 SIMD, 2 p-values)
__device__ __forceinline__ uint32_t pmaxmul(uint32_t e1p, uint32_t e1ap, uint32_t u, uint32_t v) {
    uint32_t r;
    asm("{ .reg .b32 t1, t2;\n\t"
        "mul.bf16x2 t1, %1, %3;\n\t"
        "mul.bf16x2 t2, %2, %4;\n\t"
        "max.bf16x2 %0, t1, t2; }"
        : "=r"(r) : "r"(e1p), "r"(e1ap), "r"(u), "r"(v));
    return r;
}
#define SWZ(x) ((x) ^ ((((uint32_t)(x)) >> 3) & 0x70))

// ---------------------------------------------------------------------------
// Prep 1: split x to bf16 hi/lo. 4 floats/thread.
// ---------------------------------------------------------------------------
__global__ void xsplit_kernel(const float* __restrict__ x) {
    int idx = blockIdx.x * 256 + threadIdx.x;
    float4 v = ((const float4*)x)[idx];
    uint32_t h0 = bf16pack(v.x, v.y), h1 = bf16pack(v.z, v.w);
    float l0 = v.x - __uint_as_float(h0 << 16);
    float l1 = v.y - __uint_as_float(h0 & 0xffff0000u);
    float l2 = v.z - __uint_as_float(h1 << 16);
    float l3 = v.w - __uint_as_float(h1 & 0xffff0000u);
    *(uint2*)&g_xh[(size_t)idx * 4] = make_uint2(h0, h1);
    *(uint2*)&g_xl[(size_t)idx * 4] = make_uint2(bf16pack(l0, l1), bf16pack(l2, l3));
}

// ---------------------------------------------------------------------------
// Prep 2: W [gh][512][64] -> W^T [gh][64][512] bf16 hi/lo. grid (8, 12).
// ---------------------------------------------------------------------------
__global__ void wsplit_kernel(const float* __restrict__ W) {
    __shared__ float tile[64][65];
    int t = threadIdx.x;
    int gh = blockIdx.y, f0 = blockIdx.x * 64;
    const float* Wgh = W + (size_t)gh * F_IN * NHID + (size_t)f0 * NHID;
#pragma unroll
    for (int i = 0; i < 16; i++) {
        int idx = t + 256 * i;
        tile[idx >> 6][idx & 63] = Wgh[idx];
    }
    __syncthreads();
    int o = t >> 2, fq = t & 3;
    size_t base = ((size_t)gh * 64 + o) * F_IN + f0 + fq * 16;
#pragma unroll
    for (int j = 0; j < 8; j++) {
        int f = fq * 16 + 2 * j;
        float w0 = tile[f][o], w1 = tile[f + 1][o];
        uint32_t hv = bf16pack(w0, w1);
        float l0 = w0 - __uint_as_float(hv << 16);
        float l1 = w1 - __uint_as_float(hv & 0xffff0000u);
        *(uint32_t*)&g_WTh[base + 2 * j] = hv;
        *(uint32_t*)&g_WTl[base + 2 * j] = bf16pack(l0, l1);
    }
}

// ---------------------------------------------------------------------------
// Prep 3: adj -> bitmask via ballot. 1024 ints per warp.
// ---------------------------------------------------------------------------
__global__ void adjpack_kernel(const int* __restrict__ adj) {
    int lane = threadIdx.x & 31;
    size_t wid = ((size_t)blockIdx.x * 256 + threadIdx.x) >> 5;
    size_t base = wid * 1024;
    uint32_t myw = 0;
#pragma unroll
    for (int i = 0; i < 32; i++) {
        int v = adj[base + i * 32 + lane];
        uint32_t b = __ballot_sync(0xffffffffu, v > 0);
        if (lane == i) myw = b;
    }
    g_adjbits[base / 32 + lane] = myw;
}

// ---------------------------------------------------------------------------
// Kernel 1: Wh = x @ W via mma.sync, 3-term bf16 split (fp32-accurate).
// grid (24, 12), 256 thr. Outputs g_Wh fp32 + g_WhTh bf16 transposed.
// ---------------------------------------------------------------------------
extern __shared__ char whsm[];
__global__ __launch_bounds__(256, 2) void wh_mma_kernel() {
    char* sm = whsm;
    uint32_t smb = smem_u32(sm);
    int t = threadIdx.x;
    int wid = t >> 5, lane = t & 31;
    int gh = blockIdx.y;
    int n0 = blockIdx.x * 128;

    int lrow = lane & 7, seg = lane >> 3;
    int arow = wid * 16 + lrow + (seg & 1) * 8;
    uint32_t a_sel = (uint32_t)((seg >> 1) * 16);
    int bnb = lrow + (seg >> 1) * 8;
    uint32_t b_sel = (uint32_t)((seg & 1) * 16);

    int rowA = t >> 1, halfA = t & 1;
    int ob = t >> 2, qb = t & 3;

    float acc[32];
#pragma unroll
    for (int i = 0; i < 32; i++) acc[i] = 0.f;

    for (int f0 = 0; f0 < F_IN; f0 += 64) {
        {
            const uint4* sh = (const uint4*)&g_xh[(size_t)(n0 + rowA) * F_IN + f0 + halfA * 32];
            const uint4* sl = (const uint4*)&g_xl[(size_t)(n0 + rowA) * F_IN + f0 + halfA * 32];
#pragma unroll
            for (int j = 0; j < 4; j++) {
                uint32_t s = SWZ((uint32_t)(rowA * 128 + halfA * 64 + j * 16));
                *(uint4*)(sm + s) = sh[j];
                *(uint4*)(sm + 16384 + s) = sl[j];
            }
        }
        {
            const uint4* sh = (const uint4*)&g_WTh[((size_t)gh * 64 + ob) * F_IN + f0 + qb * 16];
            const uint4* sl = (const uint4*)&g_WTl[((size_t)gh * 64 + ob) * F_IN + f0 + qb * 16];
#pragma unroll
            for (int j = 0; j < 2; j++) {
                uint32_t s = SWZ((uint32_t)(ob * 128 + qb * 32 + j * 16));
                *(uint4*)(sm + 32768 + s) = sh[j];
                *(uint4*)(sm + 40960 + s) = sl[j];
            }
        }
        __syncthreads();
#pragma unroll
        for (int ks = 0; ks < 4; ks++) {
            uint32_t ao = SWZ((uint32_t)(arow * 128 + ks * 32) + a_sel);
            uint32_t ah[4], al[4];
            ldsm4(ah, smb + ao);
            ldsm4(al, smb + 16384 + ao);
#pragma unroll
            for (int ng = 0; ng < 4; ng++) {
                uint32_t bo = SWZ((uint32_t)((ng * 16 + bnb) * 128 + ks * 32) + b_sel);
                uint32_t bh[4], bl[4];
                ldsm4(bh, smb + 32768 + bo);
                ldsm4(bl, smb + 40960 + bo);
                mma16816(acc + ng * 8, ah, bh);
                mma16816(acc + ng * 8 + 4, ah, bh + 2);
                mma16816(acc + ng * 8, ah, bl);
                mma16816(acc + ng * 8 + 4, ah, bl + 2);
                mma16816(acc + ng * 8, al, bh);
                mma16816(acc + ng * 8 + 4, al, bh + 2);
            }
        }
        __syncthreads();
    }

    int gID = lane >> 2, tig = lane & 3;
    int rA = wid * 16 + gID, rB = rA + 8;
    float* ftile = (float*)sm;  // [128][66]
#pragma unroll
    for (int ng = 0; ng < 4; ng++) {
        int col = ng * 16 + 2 * tig;
        *(float2*)&g_Wh[((size_t)gh * N + n0 + rA) * NHID + col] = make_float2(acc[ng * 8 + 0], acc[ng * 8 + 1]);
        *(float2*)&g_Wh[((size_t)gh * N + n0 + rB) * NHID + col] = make_float2(acc[ng * 8 + 2], acc[ng * 8 + 3]);
        *(float2*)&g_Wh[((size_t)gh * N + n0 + rA) * NHID + col + 8] = make_float2(acc[ng * 8 + 4], acc[ng * 8 + 5]);
        *(float2*)&g_Wh[((size_t)gh * N + n0 + rB) * NHID + col + 8] = make_float2(acc[ng * 8 + 6], acc[ng * 8 + 7]);
        ftile[rA * 66 + col] = acc[ng * 8 + 0];
        ftile[rA * 66 + col + 1] = acc[ng * 8 + 1];
        ftile[rB * 66 + col] = acc[ng * 8 + 2];
        ftile[rB * 66 + col + 1] = acc[ng * 8 + 3];
        ftile[rA * 66 + col + 8] = acc[ng * 8 + 4];
        ftile[rA * 66 + col + 9] = acc[ng * 8 + 5];
        ftile[rB * 66 + col + 8] = acc[ng * 8 + 6];
        ftile[rB * 66 + col + 9] = acc[ng * 8 + 7];
    }
    __syncthreads();
    {
        int o = t >> 2, rq = t & 3;
        size_t base = ((size_t)gh * 64 + o) * N + n0 + rq * 32;
#pragma unroll
        for (int j = 0; j < 16; j++) {
            int r = rq * 32 + 2 * j;
            *(uint32_t*)&g_WhTh[base + 2 * j] = bf16pack(ftile[r * 66 + o], ftile[(r + 1) * 66 + o]);
        }
    }
}

// ---------------------------------------------------------------------------
// Kernel 2: f1/f2 -> E1 (fp32 pair) + E2/E2a (bf16). One warp per (gh, n).
// ---------------------------------------------------------------------------
__global__ void f_kernel(const float* __restrict__ a) {
    int gh = blockIdx.y;
    int w = threadIdx.x >> 5, lane = threadIdx.x & 31;
    int n = blockIdx.x * 8 + w;
    const float* whr = g_Wh + ((size_t)gh * N + n) * NHID;
    const float* ag = a + gh * 2 * NHID;
    float wh0 = whr[lane], wh1 = whr[lane + 32];
    float s1 = wh0 * ag[lane] + wh1 * ag[lane + 32];
    float s2 = wh0 * ag[64 + lane] + wh1 * ag[96 + lane];
#pragma unroll
    for (int k = 16; k; k >>= 1) {
        s1 += __shfl_xor_sync(0xffffffffu, s1, k);
        s2 += __shfl_xor_sync(0xffffffffu, s2, k);
    }
    if (lane == 0) {
        g_E1[gh * N + n] = make_float2(__expf(s1), __expf(ALPHA * s1));
        g_E2b[gh * N + n] = __float2bfloat16(__expf(s2));
        g_E2ab[gh * N + n] = __float2bfloat16(__expf(ALPHA * s2));
    }
}

// ---------------------------------------------------------------------------
// Kernel 3: attention, bf16x2-SIMD P-stage + ones-column MMA row sums.
// grid (24, 12), 256 thr. smem: PHI 32K | BHI 16K = 48K
// ---------------------------------------------------------------------------
#define SM_PHI 0
#define SM_BHI 32768
#define ATTN_SMEM 49152
extern __shared__ char attn_sm[];
__global__ __launch_bounds__(256, 2) void attn_mma_kernel() {
    char* sm = attn_sm;
    uint32_t smb = smem_u32(sm);
    int t = threadIdx.x;
    int wid = t >> 5, lane = t & 31;
    int gh = blockIdx.y, g = gh >> 2, h = gh & 3;
    int n0 = blockIdx.x * 128;

    int row = t >> 1, half = t & 1;
    float2 E1v = g_E1[gh * N + n0 + row];
    uint32_t e1p = bf16pack(E1v.x, E1v.x);
    uint32_t e1ap = bf16pack(E1v.y, E1v.y);
    const uint32_t* bits = g_adjbits + ((size_t)g * N + n0 + row) * 96 + half * 2;
    const __nv_bfloat16* e2b = g_E2b + (size_t)gh * N + half * 64;
    const __nv_bfloat16* e2ab = g_E2ab + (size_t)gh * N + half * 64;
    uint32_t p_off = (uint32_t)(half * 16384 + row * 128);

    int ob = t >> 2, mq = t & 3;
    const __nv_bfloat16* bh_row = g_WhTh + ((size_t)gh * 64 + ob) * N + mq * 32;
    uint32_t b_off_base = (uint32_t)((mq >> 1) * 8192 + ob * 128 + (mq & 1) * 64);

    int lrow = lane & 7, seg = lane >> 3;
    int arow = wid * 16 + lrow + (seg & 1) * 8;
    uint32_t a_sel = (uint32_t)((seg >> 1) * 16);
    int bnb = lrow + (seg >> 1) * 8;
    uint32_t b_sel = (uint32_t)((seg & 1) * 16);

    const uint32_t ones2[2] = {0x3F803F80u, 0x3F803F80u};
    float acc[32], accs[4];
#pragma unroll
    for (int i = 0; i < 32; i++) acc[i] = 0.f;
#pragma unroll
    for (int i = 0; i < 4; i++) accs[i] = 0.f;

    for (int c = 0; c < 24; c++) {
        // ---- P stage: 8 m per iter, bf16x2 SIMD ----
        {
            uint2 bw = *(const uint2*)(bits + c * 4);
            const uint4* e2v = (const uint4*)(e2b + c * 128);
            const uint4* e2av = (const uint4*)(e2ab + c * 128);
#pragma unroll
            for (int i = 0; i < 8; i++) {
                uint32_t w = (i < 4) ? bw.x : bw.y;
                uint32_t byte = (w >> ((i & 3) * 8)) & 0xffu;
                uint4 u = e2v[i];
                uint4 v = e2av[i];
                uint32_t q0 = pmaxmul(e1p, e1ap, u.x, v.x);
                uint32_t q1 = pmaxmul(e1p, e1ap, u.y, v.y);
                uint32_t q2 = pmaxmul(e1p, e1ap, u.z, v.z);
                uint32_t q3 = pmaxmul(e1p, e1ap, u.w, v.w);
                uint32_t m0 = ((byte & 1u) * 0xffffu) + ((byte & 2u) * 0x7fff8000u);
                uint32_t m1 = (((byte >> 2) & 1u) * 0xffffu) + (((byte >> 2) & 2u) * 0x7fff8000u);
                uint32_t m2 = (((byte >> 4) & 1u) * 0xffffu) + (((byte >> 4) & 2u) * 0x7fff8000u);
                uint32_t m3 = (((byte >> 6) & 1u) * 0xffffu) + (((byte >> 6) & 2u) * 0x7fff8000u);
                *(uint4*)(sm + SM_PHI + SWZ(p_off + 16 * i)) =
                    make_uint4(q0 & m0, q1 & m1, q2 & m2, q3 & m3);
            }
        }
        // ---- B stage: copy pre-split WhT hi ----
        {
            const uint4* hs = (const uint4*)(bh_row + c * 128);
#pragma unroll
            for (int jj = 0; jj < 4; jj++) {
                *(uint4*)(sm + SM_BHI + SWZ(b_off_base + jj * 16)) = hs[jj];
            }
        }
        __syncthreads();
        // ---- mma (+ ones column for row sums) ----
#pragma unroll
        for (int ks = 0; ks < 8; ks++) {
            uint32_t ao = SWZ((uint32_t)((ks >> 2) * 16384 + arow * 128 + (ks & 3) * 32) + a_sel);
            uint32_t ah[4];
            ldsm4(ah, smb + SM_PHI + ao);
            mma16816(accs, ah, ones2);
            uint32_t bk = (uint32_t)((ks >> 2) * 8192 + (ks & 3) * 32) + b_sel;
#pragma unroll
            for (int ng = 0; ng < 4; ng++) {
                uint32_t bo = SWZ(bk + (uint32_t)((ng * 16 + bnb) * 128));
                uint32_t bh[4];
                ldsm4(bh, smb + SM_BHI + bo);
                mma16816(acc + ng * 8, ah, bh);
                mma16816(acc + ng * 8 + 4, ah, bh + 2);
            }
        }
        __syncthreads();
    }

    // ---- epilogue: row sums live in accs[0] (rA), accs[2] (rB) ----
    int gID = lane >> 2, tig = lane & 3;
    int rA = wid * 16 + gID, rB = rA + 8;
    float invA = 1.f / accs[0];
    float invB = 1.f / accs[2];
    float* outA = &g_hbuf[((size_t)g * N + n0 + rA) * 256 + h * 64];
    float* outB = &g_hbuf[((size_t)g * N + n0 + rB) * 256 + h * 64];
#pragma unroll
    for (int nt = 0; nt < 8; nt++) {
        int col = nt * 8 + 2 * tig;
        float v0 = acc[nt * 4 + 0] * invA;
        float v1 = acc[nt * 4 + 1] * invA;
        float v2 = acc[nt * 4 + 2] * invB;
        float v3 = acc[nt * 4 + 3] * invB;
        v0 = v0 > 0.f ? v0 : expm1f(v0);
        v1 = v1 > 0.f ? v1 : expm1f(v1);
        v2 = v2 > 0.f ? v2 : expm1f(v2);
        v3 = v3 > 0.f ? v3 : expm1f(v3);
        *(float2*)(outA + col) = make_float2(v0, v1);
        *(float2*)(outB + col) = make_float2(v2, v3);
    }
}

// ---------------------------------------------------------------------------
// Kernel 4: head. 8 nodes/block, 256 threads, d-split pairs.
// ---------------------------------------------------------------------------
__global__ void head_kernel(const float* __restrict__ W_int, const float* __restrict__ b_int,
                            const float* __restrict__ W_fus, const float* __restrict__ b_fus,
                            float* __restrict__ out) {
    __shared__ float hs[8][776];
    __shared__ float wint_s[16][260];
    __shared__ float wfus_s[16][49];
    __shared__ float xis[8][49];
    int n0 = blockIdx.x * 8;
    int t = threadIdx.x;

    for (int i = t; i < NCLASS * 64; i += 256) {
        int c = i >> 6, dq = i & 63;
        *(float4*)&wint_s[c][dq * 4] = ((const float4*)W_int)[i];
    }
    for (int i = t; i < NCLASS * 48; i += 256) wfus_s[i / 48][i % 48] = W_fus[i];
    for (int i = t; i < 8 * 192; i += 256) {
        int nl = i / 192, rq = i % 192;
        int d4 = rq * 4, g = d4 >> 8, dd = d4 & 255;
        *(float4*)&hs[nl][d4] = *(const float4*)&g_hbuf[((size_t)g * N + n0 + nl) * 256 + dd];
    }
    __syncthreads();

    int c = t & 15, halfd = (t >> 4) & 1, nl = t >> 5;
    {
        const float4* wr = (const float4*)&wint_s[c][0];
#pragma unroll
        for (int g = 0; g < NGRAPH; g++) {
            float a0 = 0.f, a1 = 0.f, a2 = 0.f, a3 = 0.f;
            const float4* hr = (const float4*)&hs[nl][g * 256];
#pragma unroll 8
            for (int d = halfd * 32; d < halfd * 32 + 32; d++) {
                float4 hv = hr[d], wv = wr[d];
                a0 = fmaf(hv.x, wv.x, a0);
                a1 = fmaf(hv.y, wv.y, a1);
                a2 = fmaf(hv.z, wv.z, a2);
                a3 = fmaf(hv.w, wv.w, a3);
            }
            float acc = (a0 + a1) + (a2 + a3);
            acc += __shfl_xor_sync(0xffffffffu, acc, 16);
            if (halfd == 0) {
                acc += b_int[c];
                xis[nl][g * 16 + c] = acc > 0.f ? acc : expm1f(acc);
            }
        }
    }
    __syncthreads();
    if (halfd == 0) {
        float acc = b_fus[c];
        const float* wr = wfus_s[c];
        const float* xr = xis[nl];
#pragma unroll
        for (int j = 0; j < 48; j++) acc = fmaf(xr[j], wr[j], acc);
        float mx = acc;
#pragma unroll
        for (int k = 8; k; k >>= 1) mx = fmaxf(mx, __shfl_xor_sync(0xffffffffu, mx, k, 16));
        float s = expf(acc - mx);
#pragma unroll
        for (int k = 8; k; k >>= 1) s += __shfl_xor_sync(0xffffffffu, s, k, 16);
        out[(size_t)(n0 + nl) * NCLASS + c] = acc - mx - logf(s);
    }
}

// ---------------------------------------------------------------------------
// Kernel 5: l1_loss = mean(|W_fus|)
// ---------------------------------------------------------------------------
__global__ void l1_kernel(const float* __restrict__ W_fus, float* __restrict__ out) {
    __shared__ float red[256];
    int t = threadIdx.x;
    float s = 0.f;
    for (int i = t; i < NCLASS * NGRAPH * NCLASS; i += 256) s += fabsf(W_fus[i]);
    red[t] = s;
    __syncthreads();
    for (int k = 128; k; k >>= 1) {
        if (t < k) red[t] += red[t + k];
        __syncthreads();
    }
    if (t == 0) out[(size_t)N * NCLASS] = red[0] / (float)(NCLASS * NGRAPH * NCLASS);
}

// ---------------------------------------------------------------------------
extern "C" void kernel_launch(void* const* d_in, const int* in_sizes, int n_in,
                              void* d_out, int out_size) {
    const float* x     = (const float*)d_in[0];
    const int*   adj   = (const int*)d_in[1];
    const float* W     = (const float*)d_in[2];
    const float* a     = (const float*)d_in[3];
    const float* W_int = (const float*)d_in[4];
    const float* b_int = (const float*)d_in[5];
    const float* W_fus = (const float*)d_in[6];
    const float* b_fus = (const float*)d_in[7];
    float* out = (float*)d_out;

    cudaFuncSetAttribute(wh_mma_kernel, cudaFuncAttributeMaxDynamicSharedMemorySize, 49152);
    cudaFuncSetAttribute(attn_mma_kernel, cudaFuncAttributeMaxDynamicSharedMemorySize, ATTN_SMEM);

    xsplit_kernel<<<N * F_IN / 1024, 256>>>(x);
    wsplit_kernel<<<dim3(F_IN / 64, NGRAPH * NHEADS), 256>>>(W);
    adjpack_kernel<<<(NGRAPH * N * N) / (8 * 1024), 256>>>(adj);
    wh_mma_kernel<<<dim3(N / 128, NGRAPH * NHEADS), 256, 49152>>>();
    f_kernel<<<dim3(N / 8, NGRAPH * NHEADS), 256>>>(a);
    attn_mma_kernel<<<dim3(N / 128, NGRAPH * NHEADS), 256, ATTN_SMEM>>>();
    head_kernel<<<N / 8, 256>>>(W_int, b_int, W_fus, b_fus, out);
    if (out_size > N * NCLASS) l1_kernel<<<1, 256>>>(W_fus, out);
}

// round 7
// speedup vs baseline: 6.2465x; 1.2035x over previous
#include <cuda_runtime.h>
#include <cuda_bf16.h>
#include <math.h>
#include <stdint.h>

#define N 3072
#define F_IN 512
#define NHID 64
#define NHEADS 4
#define NGRAPH 3
#define NCLASS 16
#define ALPHA 0.2f

// ---------------- scratch globals (no allocation) ----------------
__device__ float2 g_E1[NGRAPH * NHEADS * N];                  // {exp(f1), exp(a*f1)}
__device__ __nv_bfloat16 g_E2b[NGRAPH * NHEADS * N];          // bf16(exp(f2))
__device__ __nv_bfloat16 g_E2ab[NGRAPH * NHEADS * N];         // bf16(exp(a*f2))
__device__ __nv_bfloat16 g_WhTh[NGRAPH * NHEADS * NHID * N];  // [gh][o][m] hi (attn B)
__device__ __nv_bfloat16 g_xh[N * F_IN];                      // x bf16 hi
__device__ __nv_bfloat16 g_xl[N * F_IN];                      // x bf16 lo
__device__ __nv_bfloat16 g_WTh[NGRAPH * NHEADS * NHID * F_IN];// W^T [gh][o][f] hi
__device__ __nv_bfloat16 g_WTl[NGRAPH * NHEADS * NHID * F_IN];// W^T lo
__device__ uint32_t g_adjbits[NGRAPH * N * (N / 32)];         // adj bitmask
__device__ float g_hbuf[NGRAPH * N * NHEADS * NHID];          // [g][n][h*64+o]

// ---------------- helpers ----------------
__device__ __forceinline__ uint32_t smem_u32(const void* p) {
    uint32_t a;
    asm("{ .reg .u64 t; cvta.to.shared.u64 t, %1; cvt.u32.u64 %0, t; }" : "=r"(a) : "l"(p));
    return a;
}
__device__ __forceinline__ uint32_t bf16pack(float lo, float hi) {
    uint32_t r;
    asm("cvt.rn.satfinite.bf16x2.f32 %0, %1, %2;" : "=r"(r) : "f"(hi), "f"(lo));
    return r;  // low 16 bits = lo-arg
}
__device__ __forceinline__ void ldsm4(uint32_t* r, uint32_t addr) {
    asm volatile("ldmatrix.sync.aligned.m8n8.x4.shared.b16 {%0,%1,%2,%3}, [%4];"
                 : "=r"(r[0]), "=r"(r[1]), "=r"(r[2]), "=r"(r[3]) : "r"(addr));
}
__device__ __forceinline__ void mma16816(float* c, const uint32_t* a, const uint32_t* b) {
    asm volatile("mma.sync.aligned.m16n8k16.row.col.f32.bf16.bf16.f32 "
                 "{%0,%1,%2,%3}, {%4,%5,%6,%7}, {%8,%9}, {%0,%1,%2,%3};"
                 : "+f"(c[0]), "+f"(c[1]), "+f"(c[2]), "+f"(c[3])
                 : "r"(a[0]), "r"(a[1]), "r"(a[2]), "r"(a[3]), "r"(b[0]), "r"(b[1]));
}
__device__ __forceinline__ uint32_t pmaxmul(uint32_t e1p, uint32_t e1ap, uint32_t u, uint32_t v) {
    uint32_t r;
    asm("{ .reg .b32 t1, t2;\n\t"
        "mul.bf16x2 t1, %1, %3;\n\t"
        "mul.bf16x2 t2, %2, %4;\n\t"
        "max.bf16x2 %0, t1, t2; }"
        : "=r"(r) : "r"(e1p), "r"(e1ap), "r"(u), "r"(v));
    return r;
}
#define SWZ(x) ((x) ^ ((((uint32_t)(x)) >> 3) & 0x70))

// ---------------------------------------------------------------------------
// Prep (merged): blocks [0,1536): x split. Blocks [1536,1632): W^T split.
// ---------------------------------------------------------------------------
__global__ void prep_kernel(const float* __restrict__ x, const float* __restrict__ W) {
    int bx = blockIdx.x;
    int t = threadIdx.x;
    if (bx < 1536) {
        int idx = bx * 256 + t;
        float4 v = ((const float4*)x)[idx];
        uint32_t h0 = bf16pack(v.x, v.y), h1 = bf16pack(v.z, v.w);
        float l0 = v.x - __uint_as_float(h0 << 16);
        float l1 = v.y - __uint_as_float(h0 & 0xffff0000u);
        float l2 = v.z - __uint_as_float(h1 << 16);
        float l3 = v.w - __uint_as_float(h1 & 0xffff0000u);
        *(uint2*)&g_xh[(size_t)idx * 4] = make_uint2(h0, h1);
        *(uint2*)&g_xl[(size_t)idx * 4] = make_uint2(bf16pack(l0, l1), bf16pack(l2, l3));
    } else {
        __shared__ float tile[64][65];
        int b2 = bx - 1536;
        int gh = b2 >> 3, f0 = (b2 & 7) * 64;
        const float* Wgh = W + (size_t)gh * F_IN * NHID + (size_t)f0 * NHID;
#pragma unroll
        for (int i = 0; i < 16; i++) {
            int idx = t + 256 * i;
            tile[idx >> 6][idx & 63] = Wgh[idx];
        }
        __syncthreads();
        int o = t >> 2, fq = t & 3;
        size_t base = ((size_t)gh * 64 + o) * F_IN + f0 + fq * 16;
#pragma unroll
        for (int j = 0; j < 8; j++) {
            int f = fq * 16 + 2 * j;
            float w0 = tile[f][o], w1 = tile[f + 1][o];
            uint32_t hv = bf16pack(w0, w1);
            float l0 = w0 - __uint_as_float(hv << 16);
            float l1 = w1 - __uint_as_float(hv & 0xffff0000u);
            *(uint32_t*)&g_WTh[base + 2 * j] = hv;
            *(uint32_t*)&g_WTl[base + 2 * j] = bf16pack(l0, l1);
        }
    }
}

// ---------------------------------------------------------------------------
// Prep: adj -> bitmask via ballot.
// ---------------------------------------------------------------------------
__global__ void adjpack_kernel(const int* __restrict__ adj) {
    int lane = threadIdx.x & 31;
    size_t wid = ((size_t)blockIdx.x * 256 + threadIdx.x) >> 5;
    size_t base = wid * 1024;
    uint32_t myw = 0;
#pragma unroll
    for (int i = 0; i < 32; i++) {
        int v = adj[base + i * 32 + lane];
        uint32_t b = __ballot_sync(0xffffffffu, v > 0);
        if (lane == i) myw = b;
    }
    g_adjbits[base / 32 + lane] = myw;
}

// ---------------------------------------------------------------------------
// Kernel 1: Wh = x@W (mma.sync, 3-term split, double-buffered pipeline).
// Epilogue: WhT bf16 + f1/f2 -> E1/E2 (f_kernel folded in).
// smem: 2 x 49152 (AH|AL|BH|BL) + 512 a_s = 98816
// ---------------------------------------------------------------------------
extern __shared__ char whsm[];
__global__ __launch_bounds__(256, 2) void wh_mma_kernel(const float* __restrict__ a) {
    char* sm = whsm;
    uint32_t smb = smem_u32(sm);
    float* a_s = (float*)(sm + 98304);
    int t = threadIdx.x;
    int wid = t >> 5, lane = t & 31;
    int gh = blockIdx.y;
    int n0 = blockIdx.x * 128;

    if (t < 128) a_s[t] = a[gh * 128 + t];

    int lrow = lane & 7, seg = lane >> 3;
    int arow = wid * 16 + lrow + (seg & 1) * 8;
    uint32_t a_sel = (uint32_t)((seg >> 1) * 16);
    int bnb = lrow + (seg >> 1) * 8;
    uint32_t b_sel = (uint32_t)((seg & 1) * 16);

    int rowA = t >> 1, halfA = t & 1;
    int ob = t >> 2, qb = t & 3;

    float acc[32];
#pragma unroll
    for (int i = 0; i < 32; i++) acc[i] = 0.f;

    // stage chunk (64 k) into buffer b
    auto stage = [&](int f0, int b) {
        uint32_t bb = (uint32_t)b * 49152u;
        const uint4* sh = (const uint4*)&g_xh[(size_t)(n0 + rowA) * F_IN + f0 + halfA * 32];
        const uint4* sl = (const uint4*)&g_xl[(size_t)(n0 + rowA) * F_IN + f0 + halfA * 32];
#pragma unroll
        for (int j = 0; j < 4; j++) {
            uint32_t s = SWZ((uint32_t)(rowA * 128 + halfA * 64 + j * 16)) + bb;
            *(uint4*)(sm + s) = sh[j];
            *(uint4*)(sm + 16384 + s) = sl[j];
        }
        const uint4* th = (const uint4*)&g_WTh[((size_t)gh * 64 + ob) * F_IN + f0 + qb * 16];
        const uint4* tl = (const uint4*)&g_WTl[((size_t)gh * 64 + ob) * F_IN + f0 + qb * 16];
#pragma unroll
        for (int j = 0; j < 2; j++) {
            uint32_t s = SWZ((uint32_t)(ob * 128 + qb * 32 + j * 16)) + bb;
            *(uint4*)(sm + 32768 + s) = th[j];
            *(uint4*)(sm + 40960 + s) = tl[j];
        }
    };

    stage(0, 0);
    __syncthreads();
    for (int ci = 0; ci < 8; ci++) {
        int b = ci & 1;
        if (ci < 7) stage((ci + 1) * 64, b ^ 1);
        uint32_t bb = (uint32_t)b * 49152u;
#pragma unroll
        for (int ks = 0; ks < 4; ks++) {
            uint32_t ao = SWZ((uint32_t)(arow * 128 + ks * 32) + a_sel) + bb;
            uint32_t ah[4], al[4];
            ldsm4(ah, smb + ao);
            ldsm4(al, smb + 16384 + ao);
#pragma unroll
            for (int ng = 0; ng < 4; ng++) {
                uint32_t bo = SWZ((uint32_t)((ng * 16 + bnb) * 128 + ks * 32) + b_sel) + bb;
                uint32_t bh[4], bl[4];
                ldsm4(bh, smb + 32768 + bo);
                ldsm4(bl, smb + 40960 + bo);
                mma16816(acc + ng * 8, ah, bh);
                mma16816(acc + ng * 8 + 4, ah, bh + 2);
                mma16816(acc + ng * 8, ah, bl);
                mma16816(acc + ng * 8 + 4, ah, bl + 2);
                mma16816(acc + ng * 8, al, bh);
                mma16816(acc + ng * 8 + 4, al, bh + 2);
            }
        }
        __syncthreads();
    }

    // epilogue: ftile (fp32, buf0 region) -> WhT bf16 + f1/f2/E
    int gID = lane >> 2, tig = lane & 3;
    int rA = wid * 16 + gID, rB = rA + 8;
    float* ftile = (float*)sm;  // [128][66] = 33792 B (last mma used buf1)
#pragma unroll
    for (int ng = 0; ng < 4; ng++) {
        int col = ng * 16 + 2 * tig;
        ftile[rA * 66 + col] = acc[ng * 8 + 0];
        ftile[rA * 66 + col + 1] = acc[ng * 8 + 1];
        ftile[rB * 66 + col] = acc[ng * 8 + 2];
        ftile[rB * 66 + col + 1] = acc[ng * 8 + 3];
        ftile[rA * 66 + col + 8] = acc[ng * 8 + 4];
        ftile[rA * 66 + col + 9] = acc[ng * 8 + 5];
        ftile[rB * 66 + col + 8] = acc[ng * 8 + 6];
        ftile[rB * 66 + col + 9] = acc[ng * 8 + 7];
    }
    __syncthreads();
    {
        int o = t >> 2, rq = t & 3;
        size_t base = ((size_t)gh * 64 + o) * N + n0 + rq * 32;
#pragma unroll
        for (int j = 0; j < 16; j++) {
            int r = rq * 32 + 2 * j;
            *(uint32_t*)&g_WhTh[base + 2 * j] = bf16pack(ftile[r * 66 + o], ftile[(r + 1) * 66 + o]);
        }
    }
    // f1/f2: 2 threads per row, 32 o each
    {
        int row = t >> 1, halfo = t & 1;
        const float* fr = ftile + row * 66 + halfo * 32;
        const float* a1 = a_s + halfo * 32;
        const float* a2 = a_s + 64 + halfo * 32;
        float s1 = 0.f, s2 = 0.f;
#pragma unroll 8
        for (int o = 0; o < 32; o++) {
            float w = fr[o];
            s1 = fmaf(w, a1[o], s1);
            s2 = fmaf(w, a2[o], s2);
        }
        s1 += __shfl_xor_sync(0xffffffffu, s1, 1);
        s2 += __shfl_xor_sync(0xffffffffu, s2, 1);
        if (halfo == 0) {
            int n = n0 + row;
            g_E1[gh * N + n] = make_float2(__expf(s1), __expf(ALPHA * s1));
            g_E2b[gh * N + n] = __float2bfloat16(__expf(s2));
            g_E2ab[gh * N + n] = __float2bfloat16(__expf(ALPHA * s2));
        }
    }
}

// ---------------------------------------------------------------------------
// Kernel 2: attention. Register-direct A fragments, double-buffered B/e2.
// grid (24, 12), 256 thr. smem: B 2x16K + e2 2x1K = 34816
// ---------------------------------------------------------------------------
#define SM_B(b)   ((b) * 16384)
#define SM_E2(b)  (32768 + (b) * 1024)
#define SM_E2A(b) (32768 + (b) * 1024 + 256)
#define ATTN_SMEM 34816
extern __shared__ char attn_sm[];
__global__ __launch_bounds__(256, 2) void attn_mma_kernel() {
    char* sm = attn_sm;
    uint32_t smb = smem_u32(sm);
    int t = threadIdx.x;
    int wid = t >> 5, lane = t & 31;
    int gh = blockIdx.y, gg = gh >> 2, h = gh & 3;
    int n0 = blockIdx.x * 128;
    int g = lane >> 2, tig = lane & 3;
    int r0 = wid * 16 + g, r1 = r0 + 8;

    float2 E1v0 = g_E1[gh * N + n0 + r0];
    float2 E1v1 = g_E1[gh * N + n0 + r1];
    uint32_t e1p0 = bf16pack(E1v0.x, E1v0.x), e1ap0 = bf16pack(E1v0.y, E1v0.y);
    uint32_t e1p1 = bf16pack(E1v1.x, E1v1.x), e1ap1 = bf16pack(E1v1.y, E1v1.y);
    const uint4* bits0 = (const uint4*)(g_adjbits + ((size_t)gg * N + n0 + r0) * 96);
    const uint4* bits1 = (const uint4*)(g_adjbits + ((size_t)gg * N + n0 + r1) * 96);

    // staging ids
    int ob = t >> 2, mq = t & 3;
    const __nv_bfloat16* bh_row = g_WhTh + ((size_t)gh * 64 + ob) * N + mq * 32;
    uint32_t b_off_base = (uint32_t)((mq >> 1) * 8192 + ob * 128 + (mq & 1) * 64);
    const uint2* e2src = (const uint2*)(g_E2b + (size_t)gh * N);
    const uint2* e2asrc = (const uint2*)(g_E2ab + (size_t)gh * N);

    // B ldsm ids
    int lrow = lane & 7, seg = lane >> 3;
    int bnb = lrow + (seg >> 1) * 8;
    uint32_t b_sel = (uint32_t)((seg & 1) * 16);

    const uint32_t ones2[2] = {0x3F803F80u, 0x3F803F80u};
    float acc[32], accs[4];
#pragma unroll
    for (int i = 0; i < 32; i++) acc[i] = 0.f;
#pragma unroll
    for (int i = 0; i < 4; i++) accs[i] = 0.f;

    auto stage = [&](int c, int b) {
        const uint4* hs = (const uint4*)(bh_row + c * 128);
#pragma unroll
        for (int jj = 0; jj < 4; jj++)
            *(uint4*)(sm + SM_B(b) + SWZ(b_off_base + jj * 16)) = hs[jj];
        if (t < 32) ((uint2*)(sm + SM_E2(b)))[t] = e2src[c * 32 + t];
        else if (t < 64) ((uint2*)(sm + SM_E2A(b)))[t - 32] = e2asrc[c * 32 + (t - 32)];
    };

    stage(0, 0);
    __syncthreads();
    for (int c = 0; c < 24; c++) {
        int b = c & 1;
        if (c < 23) stage(c + 1, b ^ 1);
        uint4 w0 = bits0[c];
        uint4 w1 = bits1[c];
        const uint32_t* e2s = (const uint32_t*)(sm + SM_E2(b));
        const uint32_t* e2as = (const uint32_t*)(sm + SM_E2A(b));
#pragma unroll
        for (int ks = 0; ks < 8; ks++) {
            uint32_t mb0 = ((const uint32_t*)&w0)[ks >> 1] >> ((ks & 1) * 16);
            uint32_t mb1 = ((const uint32_t*)&w1)[ks >> 1] >> ((ks & 1) * 16);
            uint32_t ul = e2s[ks * 8 + tig], uh = e2s[ks * 8 + 4 + tig];
            uint32_t vl = e2as[ks * 8 + tig], vh = e2as[ks * 8 + 4 + tig];
            uint32_t b00 = (mb0 >> (2 * tig)) & 3u;
            uint32_t b01 = (mb0 >> (2 * tig + 8)) & 3u;
            uint32_t b10 = (mb1 >> (2 * tig)) & 3u;
            uint32_t b11 = (mb1 >> (2 * tig + 8)) & 3u;
            uint32_t af[4];
            af[0] = pmaxmul(e1p0, e1ap0, ul, vl) & ((b00 & 1u) * 0xffffu + (b00 & 2u) * 0x7fff8000u);
            af[1] = pmaxmul(e1p1, e1ap1, ul, vl) & ((b10 & 1u) * 0xffffu + (b10 & 2u) * 0x7fff8000u);
            af[2] = pmaxmul(e1p0, e1ap0, uh, vh) & ((b01 & 1u) * 0xffffu + (b01 & 2u) * 0x7fff8000u);
            af[3] = pmaxmul(e1p1, e1ap1, uh, vh) & ((b11 & 1u) * 0xffffu + (b11 & 2u) * 0x7fff8000u);
            mma16816(accs, af, ones2);
            uint32_t bk = (uint32_t)((ks >> 2) * 8192 + (ks & 3) * 32) + b_sel;
#pragma unroll
            for (int ng = 0; ng < 4; ng++) {
                uint32_t bo = SWZ(bk + (uint32_t)((ng * 16 + bnb) * 128));
                uint32_t bhf[4];
                ldsm4(bhf, smb + SM_B(b) + bo);
                mma16816(acc + ng * 8, af, bhf);
                mma16816(acc + ng * 8 + 4, af, bhf + 2);
            }
        }
        __syncthreads();
    }

    // epilogue
    int rA = r0, rB = r1;
    float invA = 1.f / accs[0];
    float invB = 1.f / accs[2];
    float* outA = &g_hbuf[((size_t)gg * N + n0 + rA) * 256 + h * 64];
    float* outB = &g_hbuf[((size_t)gg * N + n0 + rB) * 256 + h * 64];
#pragma unroll
    for (int nt = 0; nt < 8; nt++) {
        int col = nt * 8 + 2 * tig;
        float v0 = acc[nt * 4 + 0] * invA;
        float v1 = acc[nt * 4 + 1] * invA;
        float v2 = acc[nt * 4 + 2] * invB;
        float v3 = acc[nt * 4 + 3] * invB;
        v0 = v0 > 0.f ? v0 : expm1f(v0);
        v1 = v1 > 0.f ? v1 : expm1f(v1);
        v2 = v2 > 0.f ? v2 : expm1f(v2);
        v3 = v3 > 0.f ? v3 : expm1f(v3);
        *(float2*)(outA + col) = make_float2(v0, v1);
        *(float2*)(outB + col) = make_float2(v2, v3);
    }
}

// ---------------------------------------------------------------------------
// Kernel 3: head. 8 nodes/block, 256 threads, d-split pairs.
// ---------------------------------------------------------------------------
__global__ void head_kernel(const float* __restrict__ W_int, const float* __restrict__ b_int,
                            const float* __restrict__ W_fus, const float* __restrict__ b_fus,
                            float* __restrict__ out) {
    __shared__ float hs[8][776];
    __shared__ float wint_s[16][260];
    __shared__ float wfus_s[16][49];
    __shared__ float xis[8][49];
    int n0 = blockIdx.x * 8;
    int t = threadIdx.x;

    for (int i = t; i < NCLASS * 64; i += 256) {
        int c = i >> 6, dq = i & 63;
        *(float4*)&wint_s[c][dq * 4] = ((const float4*)W_int)[i];
    }
    for (int i = t; i < NCLASS * 48; i += 256) wfus_s[i / 48][i % 48] = W_fus[i];
    for (int i = t; i < 8 * 192; i += 256) {
        int nl = i / 192, rq = i % 192;
        int d4 = rq * 4, g = d4 >> 8, dd = d4 & 255;
        *(float4*)&hs[nl][d4] = *(const float4*)&g_hbuf[((size_t)g * N + n0 + nl) * 256 + dd];
    }
    __syncthreads();

    int c = t & 15, halfd = (t >> 4) & 1, nl = t >> 5;
    {
        const float4* wr = (const float4*)&wint_s[c][0];
#pragma unroll
        for (int g = 0; g < NGRAPH; g++) {
            float a0 = 0.f, a1 = 0.f, a2 = 0.f, a3 = 0.f;
            const float4* hr = (const float4*)&hs[nl][g * 256];
#pragma unroll 8
            for (int d = halfd * 32; d < halfd * 32 + 32; d++) {
                float4 hv = hr[d], wv = wr[d];
                a0 = fmaf(hv.x, wv.x, a0);
                a1 = fmaf(hv.y, wv.y, a1);
                a2 = fmaf(hv.z, wv.z, a2);
                a3 = fmaf(hv.w, wv.w, a3);
            }
            float acc = (a0 + a1) + (a2 + a3);
            acc += __shfl_xor_sync(0xffffffffu, acc, 16);
            if (halfd == 0) {
                acc += b_int[c];
                xis[nl][g * 16 + c] = acc > 0.f ? acc : expm1f(acc);
            }
        }
    }
    __syncthreads();
    if (halfd == 0) {
        float acc = b_fus[c];
        const float* wr = wfus_s[c];
        const float* xr = xis[nl];
#pragma unroll
        for (int j = 0; j < 48; j++) acc = fmaf(xr[j], wr[j], acc);
        float mx = acc;
#pragma unroll
        for (int k = 8; k; k >>= 1) mx = fmaxf(mx, __shfl_xor_sync(0xffffffffu, mx, k, 16));
        float s = expf(acc - mx);
#pragma unroll
        for (int k = 8; k; k >>= 1) s += __shfl_xor_sync(0xffffffffu, s, k, 16);
        out[(size_t)(n0 + nl) * NCLASS + c] = acc - mx - logf(s);
    }
}

// ---------------------------------------------------------------------------
// Kernel 4: l1_loss = mean(|W_fus|)
// ---------------------------------------------------------------------------
__global__ void l1_kernel(const float* __restrict__ W_fus, float* __restrict__ out) {
    __shared__ float red[256];
    int t = threadIdx.x;
    float s = 0.f;
    for (int i = t; i < NCLASS * NGRAPH * NCLASS; i += 256) s += fabsf(W_fus[i]);
    red[t] = s;
    __syncthreads();
    for (int k = 128; k; k >>= 1) {
        if (t < k) red[t] += red[t + k];
        __syncthreads();
    }
    if (t == 0) out[(size_t)N * NCLASS] = red[0] / (float)(NCLASS * NGRAPH * NCLASS);
}

// ---------------------------------------------------------------------------
extern "C" void kernel_launch(void* const* d_in, const int* in_sizes, int n_in,
                              void* d_out, int out_size) {
    const float* x     = (const float*)d_in[0];
    const int*   adj   = (const int*)d_in[1];
    const float* W     = (const float*)d_in[2];
    const float* a     = (const float*)d_in[3];
    const float* W_int = (const float*)d_in[4];
    const float* b_int = (const float*)d_in[5];
    const float* W_fus = (const float*)d_in[6];
    const float* b_fus = (const float*)d_in[7];
    float* out = (float*)d_out;

    cudaFuncSetAttribute(wh_mma_kernel, cudaFuncAttributeMaxDynamicSharedMemorySize, 98816);
    cudaFuncSetAttribute(attn_mma_kernel, cudaFuncAttributeMaxDynamicSharedMemorySize, ATTN_SMEM);

    prep_kernel<<<1632, 256>>>(x, W);
    adjpack_kernel<<<(NGRAPH * N * N) / (8 * 1024), 256>>>(adj);
    wh_mma_kernel<<<dim3(N / 128, NGRAPH * NHEADS), 256, 98816>>>(a);
    attn_mma_kernel<<<dim3(N / 128, NGRAPH * NHEADS), 256, ATTN_SMEM>>>();
    head_kernel<<<N / 8, 256>>>(W_int, b_int, W_fus, b_fus, out);
    if (out_size > N * NCLASS) l1_kernel<<<1, 256>>>(W_fus, out);
}